// round 1
// baseline (speedup 1.0000x reference)
#include <cuda_runtime.h>
#include <cuda_bf16.h>

#define TOKENS 8192
#define DM 1024
#define DFF 4096
#define NHEAD 16
#define DHEAD 64

// ---------------- scratch (device globals; no runtime alloc allowed) ----------------
__device__ float g_X[TOKENS * DM];
__device__ float g_Q[TOKENS * DM];
__device__ float g_K[TOKENS * DM];
__device__ float g_V[TOKENS * DM];
__device__ float g_CTX[TOKENS * DM];
__device__ float g_S2[TOKENS * DM];
__device__ float g_Y[TOKENS * DM];
__device__ float g_H[(size_t)TOKENS * DFF];

// ---------------- f32x2 packed-FMA helpers (ptxas never emits FFMA2 from C++) -------
__device__ __forceinline__ unsigned long long pk2(float x, float y) {
    unsigned long long r;
    asm("mov.b64 %0, {%1, %2};" : "=l"(r) : "f"(x), "f"(y));
    return r;
}
__device__ __forceinline__ void ffma2(unsigned long long& d, unsigned long long a,
                                      unsigned long long b) {
    asm("fma.rn.f32x2 %0, %1, %2, %0;" : "+l"(d) : "l"(a), "l"(b));
}
__device__ __forceinline__ float2 upk2(unsigned long long v) {
    float2 r;
    asm("mov.b64 {%0, %1}, %2;" : "=f"(r.x), "=f"(r.y) : "l"(v));
    return r;
}

// ---------------- LayerNorm: one block per row of 1024 ----------------
__global__ void __launch_bounds__(256) ln_k(const float* __restrict__ x,
                                            const float* __restrict__ g,
                                            const float* __restrict__ be,
                                            float* __restrict__ y) {
    const int row = blockIdx.x;
    const int t = threadIdx.x;
    const size_t base = (size_t)row * DM;
    const float4 v = *(const float4*)(x + base + t * 4);
    float s = v.x + v.y + v.z + v.w;
    float q = v.x * v.x + v.y * v.y + v.z * v.z + v.w * v.w;
#pragma unroll
    for (int off = 16; off; off >>= 1) {
        s += __shfl_xor_sync(0xffffffffu, s, off);
        q += __shfl_xor_sync(0xffffffffu, q, off);
    }
    __shared__ float rs[8], rq[8];
    if ((t & 31) == 0) { rs[t >> 5] = s; rq[t >> 5] = q; }
    __syncthreads();
    s = 0.f; q = 0.f;
#pragma unroll
    for (int i = 0; i < 8; ++i) { s += rs[i]; q += rq[i]; }
    const float mu = s * (1.0f / DM);
    const float var = q * (1.0f / DM) - mu * mu;
    const float r = rsqrtf(var + 1e-5f);
    const float4 gv = *(const float4*)(g + t * 4);
    const float4 bv = *(const float4*)(be + t * 4);
    float4 yv;
    yv.x = (v.x - mu) * r * gv.x + bv.x;
    yv.y = (v.y - mu) * r * gv.y + bv.y;
    yv.z = (v.z - mu) * r * gv.z + bv.z;
    yv.w = (v.w - mu) * r * gv.w + bv.w;
    *(float4*)(y + base + t * 4) = yv;
}

// ---------------- SGEMM: C[M,N] = A[M,K] @ B[K,N] + epilogue ----------------
// BM=BN=128, BK=16, 256 threads, 8x8 per-thread tile, f32x2 inner FMAs.
// EPI: 0 = +bias, 1 = relu(+bias), 2 = +bias +residual, 3 = +bias, scatter to [B*H,S,64]
#define BM 128
#define BN 128
#define BK 16

template <int EPI>
__global__ void __launch_bounds__(256, 2)
sgemm_k(const float* __restrict__ A, const float* __restrict__ Bm,
        const float* __restrict__ bias, const float* __restrict__ res,
        float* __restrict__ C, int M, int N, int K) {
    __shared__ float As[BK][BM];
    __shared__ float Bs[BK][BN];
    const int tid = threadIdx.x;
    const int bm = blockIdx.y * BM;
    const int bn = blockIdx.x * BN;
    const int tr = (tid >> 4) << 3;
    const int tc = (tid & 15) << 3;

    const int a_row = tid >> 2;
    const int a_kg = (tid & 3) << 2;
    const int b_kr = tid >> 5;
    const int b_c = (tid & 31) << 2;

    unsigned long long accp[8][4];
#pragma unroll
    for (int i = 0; i < 8; ++i)
#pragma unroll
        for (int j = 0; j < 4; ++j) accp[i][j] = 0ull;

    for (int k0 = 0; k0 < K; k0 += BK) {
#pragma unroll
        for (int h = 0; h < 2; ++h) {
            const int row = a_row + h * 64;
            const float4 v = *(const float4*)(A + (size_t)(bm + row) * K + k0 + a_kg);
            As[a_kg + 0][row] = v.x;
            As[a_kg + 1][row] = v.y;
            As[a_kg + 2][row] = v.z;
            As[a_kg + 3][row] = v.w;
        }
#pragma unroll
        for (int h = 0; h < 2; ++h) {
            const int kr = b_kr + h * 8;
            *(float4*)&Bs[kr][b_c] = *(const float4*)(Bm + (size_t)(k0 + kr) * N + bn + b_c);
        }
        __syncthreads();
#pragma unroll
        for (int kk = 0; kk < BK; ++kk) {
            const float4 a0 = *(const float4*)&As[kk][tr];
            const float4 a1 = *(const float4*)&As[kk][tr + 4];
            const float4 b0 = *(const float4*)&Bs[kk][tc];
            const float4 b1 = *(const float4*)&Bs[kk][tc + 4];
            unsigned long long bp[4];
            bp[0] = pk2(b0.x, b0.y);
            bp[1] = pk2(b0.z, b0.w);
            bp[2] = pk2(b1.x, b1.y);
            bp[3] = pk2(b1.z, b1.w);
            const float av[8] = {a0.x, a0.y, a0.z, a0.w, a1.x, a1.y, a1.z, a1.w};
#pragma unroll
            for (int i = 0; i < 8; ++i) {
                const unsigned long long ap = pk2(av[i], av[i]);
#pragma unroll
                for (int jp = 0; jp < 4; ++jp) ffma2(accp[i][jp], ap, bp[jp]);
            }
        }
        __syncthreads();
    }

    float acc[8][8];
#pragma unroll
    for (int i = 0; i < 8; ++i)
#pragma unroll
        for (int jp = 0; jp < 4; ++jp) {
            const float2 t = upk2(accp[i][jp]);
            acc[i][2 * jp] = t.x;
            acc[i][2 * jp + 1] = t.y;
        }

#pragma unroll
    for (int i = 0; i < 8; ++i) {
        const int row = bm + tr + i;
#pragma unroll
        for (int j = 0; j < 8; ++j) {
            const int col = bn + tc + j;
            float v = acc[i][j] + bias[col];
            if (EPI == 1) v = fmaxf(v, 0.0f);
            if (EPI == 2) v += res[(size_t)row * N + col];
            if (EPI == 3) {
                const int b = row >> 10, s = row & 1023;
                const int h = col >> 6, d = col & 63;
                C[(((size_t)b * NHEAD + h) * 1024 + s) * DHEAD + d] = v;
            } else {
                C[(size_t)row * N + col] = v;
            }
        }
    }
}

// ---------------- Flash attention, fp32, 64x64 tiles ----------------
// Q,K,V layout: [B*H, S, 64]. CTX written to [B, S, D].
// smem: Qs[d][q] str 68, Ks[d][kv] str 68, Ps[kv][q] str 68, Vs[kv][d] str 64
__global__ void __launch_bounds__(256) attn_k(const float* __restrict__ Q,
                                              const float* __restrict__ Kg,
                                              const float* __restrict__ Vg,
                                              float* __restrict__ CTX) {
    extern __shared__ float sm[];
    float* Qs = sm;               // 64*68 = 4352
    float* Ks = sm + 4352;        // 4352
    float* Ps = sm + 8704;        // 4352
    float* Vs = sm + 13056;       // 64*64 = 4096

    const int tid = threadIdx.x;
    const int ty = tid >> 4;      // 0..15 (q row group)
    const int tx = tid & 15;      // 0..15 (col group)
    const int bh = blockIdx.y;    // 0..127
    const int q0 = blockIdx.x << 6;
    const size_t base = (size_t)bh << 16;  // bh * 1024 * 64

    const int lrow = tid >> 4;          // loader: 16 rows per pass
    const int ld4 = (tid & 15) << 2;    // loader: d offset (float4)

    // Q tile, transposed [d][q]
#pragma unroll
    for (int it = 0; it < 4; ++it) {
        const int s = lrow + (it << 4);
        const float4 v = *(const float4*)(Q + base + (size_t)(q0 + s) * DHEAD + ld4);
        Qs[(ld4 + 0) * 68 + s] = v.x;
        Qs[(ld4 + 1) * 68 + s] = v.y;
        Qs[(ld4 + 2) * 68 + s] = v.z;
        Qs[(ld4 + 3) * 68 + s] = v.w;
    }

    float m[4], l[4];
    float4 o[4];
#pragma unroll
    for (int i = 0; i < 4; ++i) {
        m[i] = -1e30f;
        l[i] = 0.0f;
        o[i] = make_float4(0.f, 0.f, 0.f, 0.f);
    }

    for (int kt = 0; kt < 16; ++kt) {
        __syncthreads();  // previous tile compute done before overwrite
        const float* Kt = Kg + base + ((size_t)(kt << 6)) * DHEAD;
        const float* Vt = Vg + base + ((size_t)(kt << 6)) * DHEAD;
#pragma unroll
        for (int it = 0; it < 4; ++it) {
            const int s = lrow + (it << 4);
            const float4 kv = *(const float4*)(Kt + s * DHEAD + ld4);
            Ks[(ld4 + 0) * 68 + s] = kv.x;
            Ks[(ld4 + 1) * 68 + s] = kv.y;
            Ks[(ld4 + 2) * 68 + s] = kv.z;
            Ks[(ld4 + 3) * 68 + s] = kv.w;
            *(float4*)&Vs[s * 64 + ld4] = *(const float4*)(Vt + s * DHEAD + ld4);
        }
        __syncthreads();

        // S = (Q K^T) * scale, 4x4 per thread
        float s4[4][4];
#pragma unroll
        for (int i = 0; i < 4; ++i)
#pragma unroll
            for (int c = 0; c < 4; ++c) s4[i][c] = 0.f;
#pragma unroll 8
        for (int kk = 0; kk < 64; ++kk) {
            const float4 qf = *(const float4*)&Qs[kk * 68 + (ty << 2)];
            const float4 kf = *(const float4*)&Ks[kk * 68 + (tx << 2)];
            const float qa[4] = {qf.x, qf.y, qf.z, qf.w};
            const float kb[4] = {kf.x, kf.y, kf.z, kf.w};
#pragma unroll
            for (int i = 0; i < 4; ++i)
#pragma unroll
                for (int c = 0; c < 4; ++c) s4[i][c] += qa[i] * kb[c];
        }

        // online softmax per q-row (row spread over 16 lanes)
#pragma unroll
        for (int i = 0; i < 4; ++i) {
#pragma unroll
            for (int c = 0; c < 4; ++c) s4[i][c] *= 0.125f;
            float tm = fmaxf(fmaxf(s4[i][0], s4[i][1]), fmaxf(s4[i][2], s4[i][3]));
#pragma unroll
            for (int off = 8; off; off >>= 1)
                tm = fmaxf(tm, __shfl_xor_sync(0xffffffffu, tm, off));
            const float mn = fmaxf(m[i], tm);
            const float corr = __expf(m[i] - mn);
            float rsum = 0.f;
#pragma unroll
            for (int c = 0; c < 4; ++c) {
                const float p = __expf(s4[i][c] - mn);
                s4[i][c] = p;
                rsum += p;
            }
#pragma unroll
            for (int off = 8; off; off >>= 1)
                rsum += __shfl_xor_sync(0xffffffffu, rsum, off);
            l[i] = l[i] * corr + rsum;
            o[i].x *= corr; o[i].y *= corr; o[i].z *= corr; o[i].w *= corr;
            m[i] = mn;
            // write P transposed [kv][q]
#pragma unroll
            for (int c = 0; c < 4; ++c)
                Ps[((tx << 2) + c) * 68 + (ty << 2) + i] = s4[i][c];
        }
        __syncthreads();

        // O += P @ V
#pragma unroll 8
        for (int kk = 0; kk < 64; ++kk) {
            const float4 pf = *(const float4*)&Ps[kk * 68 + (ty << 2)];
            const float4 vf = *(const float4*)&Vs[kk * 64 + (tx << 2)];
            o[0].x += pf.x * vf.x; o[0].y += pf.x * vf.y; o[0].z += pf.x * vf.z; o[0].w += pf.x * vf.w;
            o[1].x += pf.y * vf.x; o[1].y += pf.y * vf.y; o[1].z += pf.y * vf.z; o[1].w += pf.y * vf.w;
            o[2].x += pf.z * vf.x; o[2].y += pf.z * vf.y; o[2].z += pf.z * vf.z; o[2].w += pf.z * vf.w;
            o[3].x += pf.w * vf.x; o[3].y += pf.w * vf.y; o[3].z += pf.w * vf.z; o[3].w += pf.w * vf.w;
        }
    }

    // epilogue: CTX[B,S,D]
    const int b = bh >> 4, h = bh & 15;
#pragma unroll
    for (int i = 0; i < 4; ++i) {
        const float inv = 1.0f / l[i];
        float4 r;
        r.x = o[i].x * inv; r.y = o[i].y * inv; r.z = o[i].z * inv; r.w = o[i].w * inv;
        const size_t off = ((size_t)(b * 1024 + q0 + (ty << 2) + i)) * DM + h * DHEAD + (tx << 2);
        *(float4*)(CTX + off) = r;
    }
}

// ---------------- launch ----------------
extern "C" void kernel_launch(void* const* d_in, const int* in_sizes, int n_in,
                              void* d_out, int out_size) {
    const float* src = (const float*)d_in[0];
    const float* Wq = (const float*)d_in[1];
    const float* bq = (const float*)d_in[2];
    const float* Wk = (const float*)d_in[3];
    const float* bk = (const float*)d_in[4];
    const float* Wv = (const float*)d_in[5];
    const float* bv = (const float*)d_in[6];
    const float* Wo = (const float*)d_in[7];
    const float* bo = (const float*)d_in[8];
    const float* W1 = (const float*)d_in[9];
    const float* b1 = (const float*)d_in[10];
    const float* W2 = (const float*)d_in[11];
    const float* b2 = (const float*)d_in[12];
    const float* g1 = (const float*)d_in[13];
    const float* be1 = (const float*)d_in[14];
    const float* g2 = (const float*)d_in[15];
    const float* be2 = (const float*)d_in[16];
    float* out = (float*)d_out;

    float *X, *Qb, *Kb, *Vb, *CT, *S2, *Y, *H;
    cudaGetSymbolAddress((void**)&X, g_X);
    cudaGetSymbolAddress((void**)&Qb, g_Q);
    cudaGetSymbolAddress((void**)&Kb, g_K);
    cudaGetSymbolAddress((void**)&Vb, g_V);
    cudaGetSymbolAddress((void**)&CT, g_CTX);
    cudaGetSymbolAddress((void**)&S2, g_S2);
    cudaGetSymbolAddress((void**)&Y, g_Y);
    cudaGetSymbolAddress((void**)&H, g_H);

    const int ATTN_SMEM = 68608;
    cudaFuncSetAttribute(attn_k, cudaFuncAttributeMaxDynamicSharedMemorySize, ATTN_SMEM);

    // 1. LN1
    ln_k<<<TOKENS, 256>>>(src, g1, be1, X);
    // 2-4. QKV projections, scatter to [B*H, S, 64]
    dim3 gdm(DM / BN, TOKENS / BM);
    sgemm_k<3><<<gdm, 256>>>(X, Wq, bq, nullptr, Qb, TOKENS, DM, DM);
    sgemm_k<3><<<gdm, 256>>>(X, Wk, bk, nullptr, Kb, TOKENS, DM, DM);
    sgemm_k<3><<<gdm, 256>>>(X, Wv, bv, nullptr, Vb, TOKENS, DM, DM);
    // 5. attention -> CTX [B,S,D]
    attn_k<<<dim3(16, 128), 256, ATTN_SMEM>>>(Qb, Kb, Vb, CT);
    // 6. Wo + residual(src) -> S2
    sgemm_k<2><<<gdm, 256>>>(CT, Wo, bo, src, S2, TOKENS, DM, DM);
    // 7. LN2
    ln_k<<<TOKENS, 256>>>(S2, g2, be2, Y);
    // 8. W1 + relu -> H
    sgemm_k<1><<<dim3(DFF / BN, TOKENS / BM), 256>>>(Y, W1, b1, nullptr, H, TOKENS, DFF, DM);
    // 9. W2 + residual(S2) -> out
    sgemm_k<2><<<gdm, 256>>>(H, W2, b2, S2, out, TOKENS, DM, DFF);
}

// round 3
// speedup vs baseline: 1.9066x; 1.9066x over previous
#include <cuda_runtime.h>
#include <cuda_bf16.h>
#include <cstdint>

#define TOKENS 8192
#define DM 1024
#define DFF 4096
#define NHEAD 16
#define DHEAD 64

// ---------------- scratch (device globals; no runtime alloc allowed) ----------------
__device__ __nv_bfloat16 g_Xh[TOKENS * DM], g_Xl[TOKENS * DM];
__device__ __nv_bfloat16 g_Yh[TOKENS * DM], g_Yl[TOKENS * DM];
__device__ __nv_bfloat16 g_Ch[TOKENS * DM], g_Cl[TOKENS * DM];
__device__ __nv_bfloat16 g_Hh[(size_t)TOKENS * DFF], g_Hl[(size_t)TOKENS * DFF];
__device__ float g_Q[TOKENS * DM];
__device__ float g_K[TOKENS * DM];
__device__ float g_V[TOKENS * DM];
__device__ float g_S2[TOKENS * DM];
// transposed + split weights: [N, K] bf16
__device__ __nv_bfloat16 g_Wqh[DM * DM], g_Wql[DM * DM];
__device__ __nv_bfloat16 g_Wkh[DM * DM], g_Wkl[DM * DM];
__device__ __nv_bfloat16 g_Wvh[DM * DM], g_Wvl[DM * DM];
__device__ __nv_bfloat16 g_Woh[DM * DM], g_Wol[DM * DM];
__device__ __nv_bfloat16 g_W1h[(size_t)DM * DFF], g_W1l[(size_t)DM * DFF];
__device__ __nv_bfloat16 g_W2h[(size_t)DM * DFF], g_W2l[(size_t)DM * DFF];

// ---------------- PTX helpers (all plain-sm_103-legal: sm_80 era) ----------------
__device__ __forceinline__ uint32_t smem_u32(const void* p) {
    uint32_t a;
    asm("{ .reg .u64 t; cvta.to.shared.u64 t, %1; cvt.u32.u64 %0, t; }" : "=r"(a) : "l"(p));
    return a;
}
__device__ __forceinline__ void cpa16(uint32_t s, const void* g) {
    asm volatile("cp.async.cg.shared.global [%0], [%1], 16;" :: "r"(s), "l"(g));
}
__device__ __forceinline__ void ldm4(uint32_t* r, uint32_t addr) {
    asm volatile("ldmatrix.sync.aligned.m8n8.x4.shared.b16 {%0,%1,%2,%3}, [%4];"
                 : "=r"(r[0]), "=r"(r[1]), "=r"(r[2]), "=r"(r[3])
                 : "r"(addr));
}
__device__ __forceinline__ void mma_bf16(float* c, const uint32_t* a, const uint32_t* b) {
    asm volatile(
        "mma.sync.aligned.m16n8k16.row.col.f32.bf16.bf16.f32 "
        "{%0,%1,%2,%3}, {%4,%5,%6,%7}, {%8,%9}, {%0,%1,%2,%3};"
        : "+f"(c[0]), "+f"(c[1]), "+f"(c[2]), "+f"(c[3])
        : "r"(a[0]), "r"(a[1]), "r"(a[2]), "r"(a[3]), "r"(b[0]), "r"(b[1]));
}
__device__ __forceinline__ void split_bf16(float v, __nv_bfloat16& h, __nv_bfloat16& l) {
    h = __float2bfloat16(v);
    l = __float2bfloat16(v - __bfloat162float(h));
}

// ---------------- weight transpose + split: W[K,N] fp32 -> T[N,K] bf16 hi/lo ----------
__global__ void __launch_bounds__(256) wconv_k(const float* __restrict__ W,
                                               __nv_bfloat16* __restrict__ Th,
                                               __nv_bfloat16* __restrict__ Tl,
                                               int K, int N) {
    __shared__ float t[32][33];
    const int bx = blockIdx.x * 32;  // N
    const int by = blockIdx.y * 32;  // K
    const int x = threadIdx.x;
    const int y0 = threadIdx.y;
#pragma unroll
    for (int dy = 0; dy < 32; dy += 8)
        t[y0 + dy][x] = W[(size_t)(by + y0 + dy) * N + bx + x];
    __syncthreads();
#pragma unroll
    for (int dy = 0; dy < 32; dy += 8) {
        const float v = t[x][y0 + dy];
        __nv_bfloat16 h, l;
        split_bf16(v, h, l);
        const size_t o = (size_t)(bx + y0 + dy) * K + by + x;
        Th[o] = h;
        Tl[o] = l;
    }
}

// ---------------- LayerNorm: writes bf16 hi/lo ----------------
__global__ void __launch_bounds__(256) ln_k(const float* __restrict__ x,
                                            const float* __restrict__ g,
                                            const float* __restrict__ be,
                                            __nv_bfloat16* __restrict__ yh,
                                            __nv_bfloat16* __restrict__ yl) {
    const int row = blockIdx.x;
    const int t = threadIdx.x;
    const size_t base = (size_t)row * DM;
    const float4 v = *(const float4*)(x + base + t * 4);
    float s = v.x + v.y + v.z + v.w;
    float q = v.x * v.x + v.y * v.y + v.z * v.z + v.w * v.w;
#pragma unroll
    for (int off = 16; off; off >>= 1) {
        s += __shfl_xor_sync(0xffffffffu, s, off);
        q += __shfl_xor_sync(0xffffffffu, q, off);
    }
    __shared__ float rs[8], rq[8];
    if ((t & 31) == 0) { rs[t >> 5] = s; rq[t >> 5] = q; }
    __syncthreads();
    s = 0.f; q = 0.f;
#pragma unroll
    for (int i = 0; i < 8; ++i) { s += rs[i]; q += rq[i]; }
    const float mu = s * (1.0f / DM);
    const float var = q * (1.0f / DM) - mu * mu;
    const float r = rsqrtf(var + 1e-5f);
    const float4 gv = *(const float4*)(g + t * 4);
    const float4 bv = *(const float4*)(be + t * 4);
    float yv[4];
    yv[0] = (v.x - mu) * r * gv.x + bv.x;
    yv[1] = (v.y - mu) * r * gv.y + bv.y;
    yv[2] = (v.z - mu) * r * gv.z + bv.z;
    yv[3] = (v.w - mu) * r * gv.w + bv.w;
    __nv_bfloat16 h[4], l[4];
#pragma unroll
    for (int i = 0; i < 4; ++i) split_bf16(yv[i], h[i], l[i]);
    __nv_bfloat162 h01, h23, l01, l23;
    h01.x = h[0]; h01.y = h[1]; h23.x = h[2]; h23.y = h[3];
    l01.x = l[0]; l01.y = l[1]; l23.x = l[2]; l23.y = l[3];
    *(__nv_bfloat162*)(yh + base + t * 4) = h01;
    *(__nv_bfloat162*)(yh + base + t * 4 + 2) = h23;
    *(__nv_bfloat162*)(yl + base + t * 4) = l01;
    *(__nv_bfloat162*)(yl + base + t * 4 + 2) = l23;
}

// ---------------- split-bf16 HMMA GEMM ----------------
// C[M,N] = A[M,K] @ B[N,K]^T.  A,B: bf16 hi/lo, K-major.  fp32 accum (mma.sync m16n8k16).
// tile 128x128, BK=32, 8 warps (2x4), warp tile 64x32, 3-stage cp.async.
// EPI: 1 relu->bf16 pair, 2 +res->fp32, 3 QKV scatter fp32
#define HBM 128
#define HBN 128
#define HBK 32
#define SROW 80              // 40 bf16 per row (padded), bytes
#define ARR 10240            // 128 * 80
#define STAGE_B (4 * ARR)    // Ah, Al, Bh, Bl
#define NSTAGE 3
#define SMEM_H (NSTAGE * STAGE_B)

template <int EPI>
__global__ void __launch_bounds__(256, 1)
hgemm(const __nv_bfloat16* __restrict__ Ah, const __nv_bfloat16* __restrict__ Al,
      const __nv_bfloat16* __restrict__ Bh, const __nv_bfloat16* __restrict__ Bl,
      const float* __restrict__ bias, const float* __restrict__ res,
      float* __restrict__ Cf, __nv_bfloat16* __restrict__ Ch, __nv_bfloat16* __restrict__ Cl,
      int M, int N, int K) {
    extern __shared__ char sm[];
    const uint32_t smb = smem_u32(sm);
    const int tid = threadIdx.x;
    const int wid = tid >> 5;
    const int lane = tid & 31;
    const int wm = wid & 1;        // 2 m-blocks of 64
    const int wn = wid >> 1;       // 4 n-blocks of 32
    const int bm = blockIdx.y * HBM;
    const int bn = blockIdx.x * HBN;
    const int nch = K / HBK;

    auto load_stage = [&](int chunk, int s) {
        const int k0 = chunk * HBK;
        const uint32_t base = smb + s * STAGE_B;
#pragma unroll
        for (int it = 0; it < 2; ++it) {
            const int idx = tid + (it << 8);       // 0..511
            const int r = idx >> 2, c4 = idx & 3;  // row, 16B chunk (4 per 64B row)
            const uint32_t dst = base + r * SROW + c4 * 16;
            const size_t goA = ((size_t)(bm + r) * K + k0 + c4 * 8) * 2;
            const size_t goB = ((size_t)(bn + r) * K + k0 + c4 * 8) * 2;
            cpa16(dst, (const char*)Ah + goA);
            cpa16(dst + ARR, (const char*)Al + goA);
            cpa16(dst + 2 * ARR, (const char*)Bh + goB);
            cpa16(dst + 3 * ARR, (const char*)Bl + goB);
        }
        asm volatile("cp.async.commit_group;");
    };

    float acc[4][4][4];
#pragma unroll
    for (int a = 0; a < 4; ++a)
#pragma unroll
        for (int b = 0; b < 4; ++b)
#pragma unroll
            for (int c = 0; c < 4; ++c) acc[a][b][c] = 0.f;

    load_stage(0, 0);
    load_stage(1, 1);

    // per-lane ldmatrix address components
    const uint32_t a_row = (lane & 15);
    const uint32_t a_koff = ((lane >> 4) << 3);
    const uint32_t b_row = (lane & 7) + (((lane >> 4) & 1) << 3);
    const uint32_t b_koff = (((lane >> 3) & 1) << 3);

    for (int i = 0; i < nch; ++i) {
        if (i + 2 < nch) load_stage(i + 2, (i + 2) % NSTAGE);
        asm volatile("cp.async.wait_group %0;" :: "n"(2));
        __syncthreads();
        const uint32_t sb = smb + (i % NSTAGE) * STAGE_B;
#pragma unroll
        for (int ks = 0; ks < 2; ++ks) {
            const int k0 = ks * 16;
            uint32_t afh[4][4], afl[4][4];
#pragma unroll
            for (int mi = 0; mi < 4; ++mi) {
                const uint32_t addr =
                    sb + (wm * 64 + mi * 16 + a_row) * SROW + (k0 + a_koff) * 2;
                ldm4(afh[mi], addr);
                ldm4(afl[mi], addr + ARR);
            }
            uint32_t bfh[2][4], bfl[2][4];
#pragma unroll
            for (int g = 0; g < 2; ++g) {
                const uint32_t addr =
                    sb + 2 * ARR + (wn * 32 + g * 16 + b_row) * SROW + (k0 + b_koff) * 2;
                ldm4(bfh[g], addr);
                ldm4(bfl[g], addr + ARR);
            }
#pragma unroll
            for (int mi = 0; mi < 4; ++mi)
#pragma unroll
                for (int ni = 0; ni < 4; ++ni) {
                    const int g = ni >> 1;
                    const int hf = (ni & 1) * 2;
                    mma_bf16(acc[mi][ni], afh[mi], &bfh[g][hf]);
                    mma_bf16(acc[mi][ni], afh[mi], &bfl[g][hf]);
                    mma_bf16(acc[mi][ni], afl[mi], &bfh[g][hf]);
                }
        }
        __syncthreads();
    }

    // epilogue
    const int er = lane >> 2;
    const int ec = (lane & 3) * 2;
#pragma unroll
    for (int mi = 0; mi < 4; ++mi)
#pragma unroll
        for (int ni = 0; ni < 4; ++ni) {
#pragma unroll
            for (int half = 0; half < 2; ++half) {
                const int row = bm + wm * 64 + mi * 16 + er + half * 8;
                const int col = bn + wn * 32 + ni * 8 + ec;
                float v0 = acc[mi][ni][half * 2 + 0] + bias[col];
                float v1 = acc[mi][ni][half * 2 + 1] + bias[col + 1];
                if (EPI == 1) {
                    v0 = fmaxf(v0, 0.f);
                    v1 = fmaxf(v1, 0.f);
                    __nv_bfloat16 h0, l0, h1, l1;
                    split_bf16(v0, h0, l0);
                    split_bf16(v1, h1, l1);
                    const size_t o = (size_t)row * N + col;
                    __nv_bfloat162 hp, lp;
                    hp.x = h0; hp.y = h1;
                    lp.x = l0; lp.y = l1;
                    *(__nv_bfloat162*)(Ch + o) = hp;
                    *(__nv_bfloat162*)(Cl + o) = lp;
                } else if (EPI == 2) {
                    const size_t o = (size_t)row * N + col;
                    const float2 rv = *(const float2*)(res + o);
                    float2 ov;
                    ov.x = v0 + rv.x;
                    ov.y = v1 + rv.y;
                    *(float2*)(Cf + o) = ov;
                } else {  // EPI == 3: scatter to [B*H, S, 64]
                    const int b = row >> 10, s = row & 1023;
                    const int h = col >> 6, d = col & 63;
                    float2 ov;
                    ov.x = v0;
                    ov.y = v1;
                    *(float2*)(Cf + (((size_t)(b * NHEAD + h) << 10) + s) * DHEAD + d) = ov;
                }
            }
        }
}

// ---------------- Flash attention, fp32, 64x64 tiles ----------------
__global__ void __launch_bounds__(256) attn_k(const float* __restrict__ Q,
                                              const float* __restrict__ Kg,
                                              const float* __restrict__ Vg,
                                              __nv_bfloat16* __restrict__ CTXh,
                                              __nv_bfloat16* __restrict__ CTXl) {
    extern __shared__ float smf[];
    float* Qs = smf;
    float* Ks = smf + 4352;
    float* Ps = smf + 8704;
    float* Vs = smf + 13056;

    const int tid = threadIdx.x;
    const int ty = tid >> 4;
    const int tx = tid & 15;
    const int bh = blockIdx.y;
    const int q0 = blockIdx.x << 6;
    const size_t base = (size_t)bh << 16;

    const int lrow = tid >> 4;
    const int ld4 = (tid & 15) << 2;

#pragma unroll
    for (int it = 0; it < 4; ++it) {
        const int s = lrow + (it << 4);
        const float4 v = *(const float4*)(Q + base + (size_t)(q0 + s) * DHEAD + ld4);
        Qs[(ld4 + 0) * 68 + s] = v.x;
        Qs[(ld4 + 1) * 68 + s] = v.y;
        Qs[(ld4 + 2) * 68 + s] = v.z;
        Qs[(ld4 + 3) * 68 + s] = v.w;
    }

    float m[4], l[4];
    float4 o[4];
#pragma unroll
    for (int i = 0; i < 4; ++i) {
        m[i] = -1e30f;
        l[i] = 0.0f;
        o[i] = make_float4(0.f, 0.f, 0.f, 0.f);
    }

    for (int kt = 0; kt < 16; ++kt) {
        __syncthreads();
        const float* Kt = Kg + base + ((size_t)(kt << 6)) * DHEAD;
        const float* Vt = Vg + base + ((size_t)(kt << 6)) * DHEAD;
#pragma unroll
        for (int it = 0; it < 4; ++it) {
            const int s = lrow + (it << 4);
            const float4 kv = *(const float4*)(Kt + s * DHEAD + ld4);
            Ks[(ld4 + 0) * 68 + s] = kv.x;
            Ks[(ld4 + 1) * 68 + s] = kv.y;
            Ks[(ld4 + 2) * 68 + s] = kv.z;
            Ks[(ld4 + 3) * 68 + s] = kv.w;
            *(float4*)&Vs[s * 64 + ld4] = *(const float4*)(Vt + s * DHEAD + ld4);
        }
        __syncthreads();

        float s4[4][4];
#pragma unroll
        for (int i = 0; i < 4; ++i)
#pragma unroll
            for (int c = 0; c < 4; ++c) s4[i][c] = 0.f;
#pragma unroll 8
        for (int kk = 0; kk < 64; ++kk) {
            const float4 qf = *(const float4*)&Qs[kk * 68 + (ty << 2)];
            const float4 kf = *(const float4*)&Ks[kk * 68 + (tx << 2)];
            const float qa[4] = {qf.x, qf.y, qf.z, qf.w};
            const float kb[4] = {kf.x, kf.y, kf.z, kf.w};
#pragma unroll
            for (int i = 0; i < 4; ++i)
#pragma unroll
                for (int c = 0; c < 4; ++c) s4[i][c] += qa[i] * kb[c];
        }

#pragma unroll
        for (int i = 0; i < 4; ++i) {
#pragma unroll
            for (int c = 0; c < 4; ++c) s4[i][c] *= 0.125f;
            float tm = fmaxf(fmaxf(s4[i][0], s4[i][1]), fmaxf(s4[i][2], s4[i][3]));
#pragma unroll
            for (int off = 8; off; off >>= 1)
                tm = fmaxf(tm, __shfl_xor_sync(0xffffffffu, tm, off));
            const float mn = fmaxf(m[i], tm);
            const float corr = __expf(m[i] - mn);
            float rsum = 0.f;
#pragma unroll
            for (int c = 0; c < 4; ++c) {
                const float p = __expf(s4[i][c] - mn);
                s4[i][c] = p;
                rsum += p;
            }
#pragma unroll
            for (int off = 8; off; off >>= 1)
                rsum += __shfl_xor_sync(0xffffffffu, rsum, off);
            l[i] = l[i] * corr + rsum;
            o[i].x *= corr; o[i].y *= corr; o[i].z *= corr; o[i].w *= corr;
            m[i] = mn;
#pragma unroll
            for (int c = 0; c < 4; ++c)
                Ps[((tx << 2) + c) * 68 + (ty << 2) + i] = s4[i][c];
        }
        __syncthreads();

#pragma unroll 8
        for (int kk = 0; kk < 64; ++kk) {
            const float4 pf = *(const float4*)&Ps[kk * 68 + (ty << 2)];
            const float4 vf = *(const float4*)&Vs[kk * 64 + (tx << 2)];
            o[0].x += pf.x * vf.x; o[0].y += pf.x * vf.y; o[0].z += pf.x * vf.z; o[0].w += pf.x * vf.w;
            o[1].x += pf.y * vf.x; o[1].y += pf.y * vf.y; o[1].z += pf.y * vf.z; o[1].w += pf.y * vf.w;
            o[2].x += pf.z * vf.x; o[2].y += pf.z * vf.y; o[2].z += pf.z * vf.z; o[2].w += pf.z * vf.w;
            o[3].x += pf.w * vf.x; o[3].y += pf.w * vf.y; o[3].z += pf.w * vf.z; o[3].w += pf.w * vf.w;
        }
    }

    const int b = bh >> 4, h = bh & 15;
#pragma unroll
    for (int i = 0; i < 4; ++i) {
        const float inv = 1.0f / l[i];
        float rv[4] = {o[i].x * inv, o[i].y * inv, o[i].z * inv, o[i].w * inv};
        const size_t off = ((size_t)(b * 1024 + q0 + (ty << 2) + i)) * DM + h * DHEAD + (tx << 2);
        __nv_bfloat16 hh[4], ll[4];
#pragma unroll
        for (int c = 0; c < 4; ++c) split_bf16(rv[c], hh[c], ll[c]);
        __nv_bfloat162 a, bq, c2, d2;
        a.x = hh[0]; a.y = hh[1]; bq.x = hh[2]; bq.y = hh[3];
        c2.x = ll[0]; c2.y = ll[1]; d2.x = ll[2]; d2.y = ll[3];
        *(__nv_bfloat162*)(CTXh + off) = a;
        *(__nv_bfloat162*)(CTXh + off + 2) = bq;
        *(__nv_bfloat162*)(CTXl + off) = c2;
        *(__nv_bfloat162*)(CTXl + off + 2) = d2;
    }
}

// ---------------- launch ----------------
extern "C" void kernel_launch(void* const* d_in, const int* in_sizes, int n_in,
                              void* d_out, int out_size) {
    const float* src = (const float*)d_in[0];
    const float* Wq = (const float*)d_in[1];
    const float* bq = (const float*)d_in[2];
    const float* Wk = (const float*)d_in[3];
    const float* bk = (const float*)d_in[4];
    const float* Wv = (const float*)d_in[5];
    const float* bv = (const float*)d_in[6];
    const float* Wo = (const float*)d_in[7];
    const float* bo = (const float*)d_in[8];
    const float* W1 = (const float*)d_in[9];
    const float* b1 = (const float*)d_in[10];
    const float* W2 = (const float*)d_in[11];
    const float* b2 = (const float*)d_in[12];
    const float* g1 = (const float*)d_in[13];
    const float* be1 = (const float*)d_in[14];
    const float* g2 = (const float*)d_in[15];
    const float* be2 = (const float*)d_in[16];
    float* out = (float*)d_out;

#define SYM(p, s) cudaGetSymbolAddress((void**)&p, s)
    __nv_bfloat16 *Xh, *Xl, *Yh, *Yl, *Chb, *Clb, *Hh, *Hl;
    __nv_bfloat16 *Wqh, *Wql, *Wkh, *Wkl, *Wvh, *Wvl, *Woh, *Wol, *W1h, *W1l, *W2h, *W2l;
    float *Qb, *Kb, *Vb, *S2;
    SYM(Xh, g_Xh); SYM(Xl, g_Xl); SYM(Yh, g_Yh); SYM(Yl, g_Yl);
    SYM(Chb, g_Ch); SYM(Clb, g_Cl); SYM(Hh, g_Hh); SYM(Hl, g_Hl);
    SYM(Qb, g_Q); SYM(Kb, g_K); SYM(Vb, g_V); SYM(S2, g_S2);
    SYM(Wqh, g_Wqh); SYM(Wql, g_Wql); SYM(Wkh, g_Wkh); SYM(Wkl, g_Wkl);
    SYM(Wvh, g_Wvh); SYM(Wvl, g_Wvl); SYM(Woh, g_Woh); SYM(Wol, g_Wol);
    SYM(W1h, g_W1h); SYM(W1l, g_W1l); SYM(W2h, g_W2h); SYM(W2l, g_W2l);
#undef SYM

    const int ATTN_SMEM = 68608;
    cudaFuncSetAttribute(attn_k, cudaFuncAttributeMaxDynamicSharedMemorySize, ATTN_SMEM);
    cudaFuncSetAttribute(hgemm<1>, cudaFuncAttributeMaxDynamicSharedMemorySize, SMEM_H);
    cudaFuncSetAttribute(hgemm<2>, cudaFuncAttributeMaxDynamicSharedMemorySize, SMEM_H);
    cudaFuncSetAttribute(hgemm<3>, cudaFuncAttributeMaxDynamicSharedMemorySize, SMEM_H);

    // weight transpose+split
    dim3 cb(32, 8);
    wconv_k<<<dim3(DM / 32, DM / 32), cb>>>(Wq, Wqh, Wql, DM, DM);
    wconv_k<<<dim3(DM / 32, DM / 32), cb>>>(Wk, Wkh, Wkl, DM, DM);
    wconv_k<<<dim3(DM / 32, DM / 32), cb>>>(Wv, Wvh, Wvl, DM, DM);
    wconv_k<<<dim3(DM / 32, DM / 32), cb>>>(Wo, Woh, Wol, DM, DM);
    wconv_k<<<dim3(DFF / 32, DM / 32), cb>>>(W1, W1h, W1l, DM, DFF);
    wconv_k<<<dim3(DM / 32, DFF / 32), cb>>>(W2, W2h, W2l, DFF, DM);

    // LN1 -> X (bf16 pair)
    ln_k<<<TOKENS, 256>>>(src, g1, be1, Xh, Xl);

    // QKV projections (EPI=3 scatter to [B*H,S,64] fp32)
    dim3 gqkv(DM / HBN, TOKENS / HBM);
    hgemm<3><<<gqkv, 256, SMEM_H>>>(Xh, Xl, Wqh, Wql, bq, nullptr, Qb, nullptr, nullptr,
                                    TOKENS, DM, DM);
    hgemm<3><<<gqkv, 256, SMEM_H>>>(Xh, Xl, Wkh, Wkl, bk, nullptr, Kb, nullptr, nullptr,
                                    TOKENS, DM, DM);
    hgemm<3><<<gqkv, 256, SMEM_H>>>(Xh, Xl, Wvh, Wvl, bv, nullptr, Vb, nullptr, nullptr,
                                    TOKENS, DM, DM);

    // attention -> CTX bf16 pair
    attn_k<<<dim3(16, 128), 256, ATTN_SMEM>>>(Qb, Kb, Vb, Chb, Clb);

    // Wo + residual(src) -> S2 fp32
    hgemm<2><<<gqkv, 256, SMEM_H>>>(Chb, Clb, Woh, Wol, bo, src, S2, nullptr, nullptr,
                                    TOKENS, DM, DM);

    // LN2 -> Y bf16 pair
    ln_k<<<TOKENS, 256>>>(S2, g2, be2, Yh, Yl);

    // W1 + relu -> H bf16 pair
    hgemm<1><<<dim3(DFF / HBN, TOKENS / HBM), 256, SMEM_H>>>(
        Yh, Yl, W1h, W1l, b1, nullptr, nullptr, Hh, Hl, TOKENS, DFF, DM);

    // W2 + residual(S2) -> out fp32
    hgemm<2><<<gqkv, 256, SMEM_H>>>(Hh, Hl, W2h, W2l, b2, S2, out, nullptr, nullptr,
                                    TOKENS, DM, DFF);
}

// round 5
// speedup vs baseline: 1.9673x; 1.0318x over previous
#include <cuda_runtime.h>
#include <cuda_bf16.h>
#include <cstdint>

#define TOKENS 8192
#define DM 1024
#define DFF 4096
#define NHEAD 16
#define DHEAD 64

// ---------------- scratch (device globals; no runtime alloc allowed) ----------------
__device__ __nv_bfloat16 g_Xh[TOKENS * DM], g_Xl[TOKENS * DM];
__device__ __nv_bfloat16 g_Yh[TOKENS * DM], g_Yl[TOKENS * DM];
__device__ __nv_bfloat16 g_Ch[TOKENS * DM], g_Cl[TOKENS * DM];
__device__ __nv_bfloat16 g_Hh[(size_t)TOKENS * DFF], g_Hl[(size_t)TOKENS * DFF];
__device__ float g_Q[TOKENS * DM];
__device__ float g_K[TOKENS * DM];
__device__ float g_V[TOKENS * DM];
__device__ float g_S2[TOKENS * DM];
__device__ float g_bqkv[3 * DM];
// transposed + split weights: [N, K] bf16
__device__ __nv_bfloat16 g_Wqkvh[3 * DM * DM], g_Wqkvl[3 * DM * DM];
__device__ __nv_bfloat16 g_Woh[DM * DM], g_Wol[DM * DM];
__device__ __nv_bfloat16 g_W1h[(size_t)DM * DFF], g_W1l[(size_t)DM * DFF];
__device__ __nv_bfloat16 g_W2h[(size_t)DM * DFF], g_W2l[(size_t)DM * DFF];

// ---------------- PTX helpers ----------------
__device__ __forceinline__ uint32_t smem_u32(const void* p) {
    uint32_t a;
    asm("{ .reg .u64 t; cvta.to.shared.u64 t, %1; cvt.u32.u64 %0, t; }" : "=r"(a) : "l"(p));
    return a;
}
__device__ __forceinline__ void cpa16(uint32_t s, const void* g) {
    asm volatile("cp.async.cg.shared.global [%0], [%1], 16;" :: "r"(s), "l"(g));
}
__device__ __forceinline__ void ldm4(uint32_t* r, uint32_t addr) {
    asm volatile("ldmatrix.sync.aligned.m8n8.x4.shared.b16 {%0,%1,%2,%3}, [%4];"
                 : "=r"(r[0]), "=r"(r[1]), "=r"(r[2]), "=r"(r[3])
                 : "r"(addr));
}
__device__ __forceinline__ void mma_bf16(float* c, const uint32_t* a, const uint32_t* b) {
    asm volatile(
        "mma.sync.aligned.m16n8k16.row.col.f32.bf16.bf16.f32 "
        "{%0,%1,%2,%3}, {%4,%5,%6,%7}, {%8,%9}, {%0,%1,%2,%3};"
        : "+f"(c[0]), "+f"(c[1]), "+f"(c[2]), "+f"(c[3])
        : "r"(a[0]), "r"(a[1]), "r"(a[2]), "r"(a[3]), "r"(b[0]), "r"(b[1]));
}
__device__ __forceinline__ void split_bf16(float v, __nv_bfloat16& h, __nv_bfloat16& l) {
    h = __float2bfloat16(v);
    l = __float2bfloat16(v - __bfloat162float(h));
}

// ---------------- weight transpose + split: W[K,N] fp32 -> T[N,K] bf16 hi/lo ----------
__global__ void __launch_bounds__(256) wconv_k(const float* __restrict__ W,
                                               __nv_bfloat16* __restrict__ Th,
                                               __nv_bfloat16* __restrict__ Tl,
                                               int K, int N) {
    __shared__ float t[32][33];
    const int bx = blockIdx.x * 32;  // N
    const int by = blockIdx.y * 32;  // K
    const int x = threadIdx.x;
    const int y0 = threadIdx.y;
#pragma unroll
    for (int dy = 0; dy < 32; dy += 8)
        t[y0 + dy][x] = W[(size_t)(by + y0 + dy) * N + bx + x];
    __syncthreads();
#pragma unroll
    for (int dy = 0; dy < 32; dy += 8) {
        const float v = t[x][y0 + dy];
        __nv_bfloat16 h, l;
        split_bf16(v, h, l);
        const size_t o = (size_t)(bx + y0 + dy) * K + by + x;
        Th[o] = h;
        Tl[o] = l;
    }
}

// ---------------- bias concat for fused QKV ----------------
__global__ void biascat_k(const float* __restrict__ a, const float* __restrict__ b,
                          const float* __restrict__ c, float* __restrict__ o) {
    const int i = blockIdx.x * 256 + threadIdx.x;
    if (i < DM) o[i] = a[i];
    else if (i < 2 * DM) o[i] = b[i - DM];
    else o[i] = c[i - 2 * DM];
}

// ---------------- LayerNorm: writes bf16 hi/lo ----------------
__global__ void __launch_bounds__(256) ln_k(const float* __restrict__ x,
                                            const float* __restrict__ g,
                                            const float* __restrict__ be,
                                            __nv_bfloat16* __restrict__ yh,
                                            __nv_bfloat16* __restrict__ yl) {
    const int row = blockIdx.x;
    const int t = threadIdx.x;
    const size_t base = (size_t)row * DM;
    const float4 v = *(const float4*)(x + base + t * 4);
    float s = v.x + v.y + v.z + v.w;
    float q = v.x * v.x + v.y * v.y + v.z * v.z + v.w * v.w;
#pragma unroll
    for (int off = 16; off; off >>= 1) {
        s += __shfl_xor_sync(0xffffffffu, s, off);
        q += __shfl_xor_sync(0xffffffffu, q, off);
    }
    __shared__ float rs[8], rq[8];
    if ((t & 31) == 0) { rs[t >> 5] = s; rq[t >> 5] = q; }
    __syncthreads();
    s = 0.f; q = 0.f;
#pragma unroll
    for (int i = 0; i < 8; ++i) { s += rs[i]; q += rq[i]; }
    const float mu = s * (1.0f / DM);
    const float var = q * (1.0f / DM) - mu * mu;
    const float r = rsqrtf(var + 1e-5f);
    const float4 gv = *(const float4*)(g + t * 4);
    const float4 bv = *(const float4*)(be + t * 4);
    float yv[4];
    yv[0] = (v.x - mu) * r * gv.x + bv.x;
    yv[1] = (v.y - mu) * r * gv.y + bv.y;
    yv[2] = (v.z - mu) * r * gv.z + bv.z;
    yv[3] = (v.w - mu) * r * gv.w + bv.w;
    __nv_bfloat16 h[4], l[4];
#pragma unroll
    for (int i = 0; i < 4; ++i) split_bf16(yv[i], h[i], l[i]);
    __nv_bfloat162 h01, h23, l01, l23;
    h01.x = h[0]; h01.y = h[1]; h23.x = h[2]; h23.y = h[3];
    l01.x = l[0]; l01.y = l[1]; l23.x = l[2]; l23.y = l[3];
    *(__nv_bfloat162*)(yh + base + t * 4) = h01;
    *(__nv_bfloat162*)(yh + base + t * 4 + 2) = h23;
    *(__nv_bfloat162*)(yl + base + t * 4) = l01;
    *(__nv_bfloat162*)(yl + base + t * 4 + 2) = l23;
}

// ---------------- split-bf16 HMMA GEMM, templated N-tile ----------------
// C[M,N] = A[M,K] @ B[N,K]^T.  tile 128 x BN_, BK=32, 8 warps (2x4), 3-stage cp.async.
// EPI: 1 relu->bf16 pair, 2 +res->fp32, 3 fused-QKV scatter fp32 (col>>10 picks Q/K/V)
#define HBK 32
#define SROW 80
#define A_BYTES 10240  // 128 * 80

template <int EPI, int BN_>
__global__ void __launch_bounds__(256, 1)
hgemm(const __nv_bfloat16* __restrict__ Ah, const __nv_bfloat16* __restrict__ Al,
      const __nv_bfloat16* __restrict__ Bh, const __nv_bfloat16* __restrict__ Bl,
      const float* __restrict__ bias, const float* __restrict__ res,
      float* __restrict__ Cf, float* __restrict__ Cf2, float* __restrict__ Cf3,
      __nv_bfloat16* __restrict__ Ch, __nv_bfloat16* __restrict__ Cl,
      int M, int N, int K) {
    constexpr int WT_N = BN_ / 4;       // warp n extent: 32 or 64
    constexpr int NG = WT_N / 16;       // 16-wide b-groups: 2 or 4
    constexpr int NI = WT_N / 8;        // 8-wide mma cols: 4 or 8
    constexpr int B_BYTES = BN_ * SROW;
    constexpr int STAGE_B = 2 * A_BYTES + 2 * B_BYTES;

    extern __shared__ char sm[];
    const uint32_t smb = smem_u32(sm);
    const int tid = threadIdx.x;
    const int wid = tid >> 5;
    const int lane = tid & 31;
    const int wm = wid & 1;
    const int wn = wid >> 1;
    const int bm = blockIdx.y * 128;
    const int bn = blockIdx.x * BN_;
    const int nch = K / HBK;

    auto load_stage = [&](int chunk, int s) {
        const int k0 = chunk * HBK;
        const uint32_t base = smb + s * STAGE_B;
        constexpr int ITER = (128 + BN_) * 4 / 256;
#pragma unroll
        for (int it = 0; it < ITER; ++it) {
            const int idx = tid + (it << 8);
            const int r = idx >> 2, c4 = idx & 3;
            if (r < 128) {
                const uint32_t dst = base + r * SROW + c4 * 16;
                const size_t go = ((size_t)(bm + r) * K + k0 + c4 * 8) * 2;
                cpa16(dst, (const char*)Ah + go);
                cpa16(dst + A_BYTES, (const char*)Al + go);
            } else {
                const int rb = r - 128;
                const uint32_t dst = base + 2 * A_BYTES + rb * SROW + c4 * 16;
                const size_t go = ((size_t)(bn + rb) * K + k0 + c4 * 8) * 2;
                cpa16(dst, (const char*)Bh + go);
                cpa16(dst + B_BYTES, (const char*)Bl + go);
            }
        }
        asm volatile("cp.async.commit_group;");
    };

    float acc[4][NI][4];
#pragma unroll
    for (int a = 0; a < 4; ++a)
#pragma unroll
        for (int b = 0; b < NI; ++b)
#pragma unroll
            for (int c = 0; c < 4; ++c) acc[a][b][c] = 0.f;

    load_stage(0, 0);
    load_stage(1, 1);

    const uint32_t a_row = (lane & 15);
    const uint32_t a_koff = ((lane >> 4) << 3);
    const uint32_t b_row = (lane & 7) + (((lane >> 4) & 1) << 3);
    const uint32_t b_koff = (((lane >> 3) & 1) << 3);

    for (int i = 0; i < nch; ++i) {
        if (i + 2 < nch) load_stage(i + 2, (i + 2) % 3);
        asm volatile("cp.async.wait_group %0;" :: "n"(2));
        __syncthreads();
        const uint32_t sb = smb + (i % 3) * STAGE_B;
#pragma unroll
        for (int ks = 0; ks < 2; ++ks) {
            const int k0 = ks * 16;
            uint32_t afh[4][4], afl[4][4];
#pragma unroll
            for (int mi = 0; mi < 4; ++mi) {
                const uint32_t addr =
                    sb + (wm * 64 + mi * 16 + a_row) * SROW + (k0 + a_koff) * 2;
                ldm4(afh[mi], addr);
                ldm4(afl[mi], addr + A_BYTES);
            }
            uint32_t bfh[NG][4], bfl[NG][4];
#pragma unroll
            for (int g = 0; g < NG; ++g) {
                const uint32_t addr =
                    sb + 2 * A_BYTES + (wn * WT_N + g * 16 + b_row) * SROW + (k0 + b_koff) * 2;
                ldm4(bfh[g], addr);
                ldm4(bfl[g], addr + B_BYTES);
            }
#pragma unroll
            for (int mi = 0; mi < 4; ++mi)
#pragma unroll
                for (int ni = 0; ni < NI; ++ni) {
                    const int g = ni >> 1;
                    const int hf = (ni & 1) * 2;
                    mma_bf16(acc[mi][ni], afh[mi], &bfh[g][hf]);
                    mma_bf16(acc[mi][ni], afh[mi], &bfl[g][hf]);
                    mma_bf16(acc[mi][ni], afl[mi], &bfh[g][hf]);
                }
        }
        __syncthreads();
    }

    // epilogue
    const int er = lane >> 2;
    const int ec = (lane & 3) * 2;
#pragma unroll
    for (int mi = 0; mi < 4; ++mi)
#pragma unroll
        for (int ni = 0; ni < NI; ++ni) {
#pragma unroll
            for (int half = 0; half < 2; ++half) {
                const int row = bm + wm * 64 + mi * 16 + er + half * 8;
                const int col = bn + wn * WT_N + ni * 8 + ec;
                float v0 = acc[mi][ni][half * 2 + 0] + bias[col];
                float v1 = acc[mi][ni][half * 2 + 1] + bias[col + 1];
                if (EPI == 1) {
                    v0 = fmaxf(v0, 0.f);
                    v1 = fmaxf(v1, 0.f);
                    __nv_bfloat16 h0, l0, h1, l1;
                    split_bf16(v0, h0, l0);
                    split_bf16(v1, h1, l1);
                    const size_t o = (size_t)row * N + col;
                    __nv_bfloat162 hp, lp;
                    hp.x = h0; hp.y = h1;
                    lp.x = l0; lp.y = l1;
                    *(__nv_bfloat162*)(Ch + o) = hp;
                    *(__nv_bfloat162*)(Cl + o) = lp;
                } else if (EPI == 2) {
                    const size_t o = (size_t)row * N + col;
                    const float2 rv = *(const float2*)(res + o);
                    float2 ov;
                    ov.x = v0 + rv.x;
                    ov.y = v1 + rv.y;
                    *(float2*)(Cf + o) = ov;
                } else {  // EPI == 3: fused QKV scatter to [B*H, S, 64]
                    const int t = col >> 10;
                    const int cc = col & 1023;
                    const int b = row >> 10, s = row & 1023;
                    const int h = cc >> 6, d = cc & 63;
                    float* dst = (t == 0) ? Cf : (t == 1) ? Cf2 : Cf3;
                    float2 ov;
                    ov.x = v0;
                    ov.y = v1;
                    *(float2*)(dst + (((size_t)(b * NHEAD + h) << 10) + s) * DHEAD + d) = ov;
                }
            }
        }
}

// ---------------- Flash attention, fp32, 64x64 tiles ----------------
__global__ void __launch_bounds__(256) attn_k(const float* __restrict__ Q,
                                              const float* __restrict__ Kg,
                                              const float* __restrict__ Vg,
                                              __nv_bfloat16* __restrict__ CTXh,
                                              __nv_bfloat16* __restrict__ CTXl) {
    extern __shared__ float smf[];
    float* Qs = smf;
    float* Ks = smf + 4352;
    float* Ps = smf + 8704;
    float* Vs = smf + 13056;

    const int tid = threadIdx.x;
    const int ty = tid >> 4;
    const int tx = tid & 15;
    const int bh = blockIdx.y;
    const int q0 = blockIdx.x << 6;
    const size_t base = (size_t)bh << 16;

    const int lrow = tid >> 4;
    const int ld4 = (tid & 15) << 2;

#pragma unroll
    for (int it = 0; it < 4; ++it) {
        const int s = lrow + (it << 4);
        const float4 v = *(const float4*)(Q + base + (size_t)(q0 + s) * DHEAD + ld4);
        Qs[(ld4 + 0) * 68 + s] = v.x;
        Qs[(ld4 + 1) * 68 + s] = v.y;
        Qs[(ld4 + 2) * 68 + s] = v.z;
        Qs[(ld4 + 3) * 68 + s] = v.w;
    }

    float m[4], l[4];
    float4 o[4];
#pragma unroll
    for (int i = 0; i < 4; ++i) {
        m[i] = -1e30f;
        l[i] = 0.0f;
        o[i] = make_float4(0.f, 0.f, 0.f, 0.f);
    }

    for (int kt = 0; kt < 16; ++kt) {
        __syncthreads();
        const float* Kt = Kg + base + ((size_t)(kt << 6)) * DHEAD;
        const float* Vt = Vg + base + ((size_t)(kt << 6)) * DHEAD;
#pragma unroll
        for (int it = 0; it < 4; ++it) {
            const int s = lrow + (it << 4);
            const float4 kv = *(const float4*)(Kt + s * DHEAD + ld4);
            Ks[(ld4 + 0) * 68 + s] = kv.x;
            Ks[(ld4 + 1) * 68 + s] = kv.y;
            Ks[(ld4 + 2) * 68 + s] = kv.z;
            Ks[(ld4 + 3) * 68 + s] = kv.w;
            *(float4*)&Vs[s * 64 + ld4] = *(const float4*)(Vt + s * DHEAD + ld4);
        }
        __syncthreads();

        float s4[4][4];
#pragma unroll
        for (int i = 0; i < 4; ++i)
#pragma unroll
            for (int c = 0; c < 4; ++c) s4[i][c] = 0.f;
#pragma unroll 8
        for (int kk = 0; kk < 64; ++kk) {
            const float4 qf = *(const float4*)&Qs[kk * 68 + (ty << 2)];
            const float4 kf = *(const float4*)&Ks[kk * 68 + (tx << 2)];
            const float qa[4] = {qf.x, qf.y, qf.z, qf.w};
            const float kb[4] = {kf.x, kf.y, kf.z, kf.w};
#pragma unroll
            for (int i = 0; i < 4; ++i)
#pragma unroll
                for (int c = 0; c < 4; ++c) s4[i][c] += qa[i] * kb[c];
        }

#pragma unroll
        for (int i = 0; i < 4; ++i) {
#pragma unroll
            for (int c = 0; c < 4; ++c) s4[i][c] *= 0.125f;
            float tm = fmaxf(fmaxf(s4[i][0], s4[i][1]), fmaxf(s4[i][2], s4[i][3]));
#pragma unroll
            for (int off = 8; off; off >>= 1)
                tm = fmaxf(tm, __shfl_xor_sync(0xffffffffu, tm, off));
            const float mn = fmaxf(m[i], tm);
            const float corr = __expf(m[i] - mn);
            float rsum = 0.f;
#pragma unroll
            for (int c = 0; c < 4; ++c) {
                const float p = __expf(s4[i][c] - mn);
                s4[i][c] = p;
                rsum += p;
            }
#pragma unroll
            for (int off = 8; off; off >>= 1)
                rsum += __shfl_xor_sync(0xffffffffu, rsum, off);
            l[i] = l[i] * corr + rsum;
            o[i].x *= corr; o[i].y *= corr; o[i].z *= corr; o[i].w *= corr;
            m[i] = mn;
#pragma unroll
            for (int c = 0; c < 4; ++c)
                Ps[((tx << 2) + c) * 68 + (ty << 2) + i] = s4[i][c];
        }
        __syncthreads();

#pragma unroll 8
        for (int kk = 0; kk < 64; ++kk) {
            const float4 pf = *(const float4*)&Ps[kk * 68 + (ty << 2)];
            const float4 vf = *(const float4*)&Vs[kk * 64 + (tx << 2)];
            o[0].x += pf.x * vf.x; o[0].y += pf.x * vf.y; o[0].z += pf.x * vf.z; o[0].w += pf.x * vf.w;
            o[1].x += pf.y * vf.x; o[1].y += pf.y * vf.y; o[1].z += pf.y * vf.z; o[1].w += pf.y * vf.w;
            o[2].x += pf.z * vf.x; o[2].y += pf.z * vf.y; o[2].z += pf.z * vf.z; o[2].w += pf.z * vf.w;
            o[3].x += pf.w * vf.x; o[3].y += pf.w * vf.y; o[3].z += pf.w * vf.z; o[3].w += pf.w * vf.w;
        }
    }

    const int b = bh >> 4, h = bh & 15;
#pragma unroll
    for (int i = 0; i < 4; ++i) {
        const float inv = 1.0f / l[i];
        float rv[4] = {o[i].x * inv, o[i].y * inv, o[i].z * inv, o[i].w * inv};
        const size_t off = ((size_t)(b * 1024 + q0 + (ty << 2) + i)) * DM + h * DHEAD + (tx << 2);
        __nv_bfloat16 hh[4], ll[4];
#pragma unroll
        for (int c = 0; c < 4; ++c) split_bf16(rv[c], hh[c], ll[c]);
        __nv_bfloat162 a, bq, c2, d2;
        a.x = hh[0]; a.y = hh[1]; bq.x = hh[2]; bq.y = hh[3];
        c2.x = ll[0]; c2.y = ll[1]; d2.x = ll[2]; d2.y = ll[3];
        *(__nv_bfloat162*)(CTXh + off) = a;
        *(__nv_bfloat162*)(CTXh + off + 2) = bq;
        *(__nv_bfloat162*)(CTXl + off) = c2;
        *(__nv_bfloat162*)(CTXl + off + 2) = d2;
    }
}

// ---------------- launch ----------------
extern "C" void kernel_launch(void* const* d_in, const int* in_sizes, int n_in,
                              void* d_out, int out_size) {
    const float* src = (const float*)d_in[0];
    const float* Wq = (const float*)d_in[1];
    const float* bq = (const float*)d_in[2];
    const float* Wk = (const float*)d_in[3];
    const float* bk = (const float*)d_in[4];
    const float* Wv = (const float*)d_in[5];
    const float* bv = (const float*)d_in[6];
    const float* Wo = (const float*)d_in[7];
    const float* bo = (const float*)d_in[8];
    const float* W1 = (const float*)d_in[9];
    const float* b1 = (const float*)d_in[10];
    const float* W2 = (const float*)d_in[11];
    const float* b2 = (const float*)d_in[12];
    const float* g1 = (const float*)d_in[13];
    const float* be1 = (const float*)d_in[14];
    const float* g2 = (const float*)d_in[15];
    const float* be2 = (const float*)d_in[16];
    float* out = (float*)d_out;

#define SYM(p, s) cudaGetSymbolAddress((void**)&p, s)
    __nv_bfloat16 *Xh, *Xl, *Yh, *Yl, *Chb, *Clb, *Hh, *Hl;
    __nv_bfloat16 *Wqkvh, *Wqkvl, *Woh, *Wol, *W1h, *W1l, *W2h, *W2l;
    float *Qb, *Kb, *Vb, *S2, *bqkv;
    SYM(Xh, g_Xh); SYM(Xl, g_Xl); SYM(Yh, g_Yh); SYM(Yl, g_Yl);
    SYM(Chb, g_Ch); SYM(Clb, g_Cl); SYM(Hh, g_Hh); SYM(Hl, g_Hl);
    SYM(Qb, g_Q); SYM(Kb, g_K); SYM(Vb, g_V); SYM(S2, g_S2); SYM(bqkv, g_bqkv);
    SYM(Wqkvh, g_Wqkvh); SYM(Wqkvl, g_Wqkvl);
    SYM(Woh, g_Woh); SYM(Wol, g_Wol);
    SYM(W1h, g_W1h); SYM(W1l, g_W1l); SYM(W2h, g_W2h); SYM(W2l, g_W2l);
#undef SYM

    const int ATTN_SMEM = 68608;
    const int SMEM_256 = 3 * (2 * A_BYTES + 2 * 256 * SROW);  // 184320
    const int SMEM_128 = 3 * (2 * A_BYTES + 2 * 128 * SROW);  // 122880
    cudaFuncSetAttribute(attn_k, cudaFuncAttributeMaxDynamicSharedMemorySize, ATTN_SMEM);
    cudaFuncSetAttribute(hgemm<3, 256>, cudaFuncAttributeMaxDynamicSharedMemorySize, SMEM_256);
    cudaFuncSetAttribute(hgemm<1, 256>, cudaFuncAttributeMaxDynamicSharedMemorySize, SMEM_256);
    cudaFuncSetAttribute(hgemm<2, 128>, cudaFuncAttributeMaxDynamicSharedMemorySize, SMEM_128);

    dim3 cb(32, 8);
    // launches 0-4 (ncu -s 5 captures launch #5 = fused QKV hgemm)
    wconv_k<<<dim3(DM / 32, DM / 32), cb>>>(Wq, Wqkvh, Wqkvl, DM, DM);
    wconv_k<<<dim3(DM / 32, DM / 32), cb>>>(Wk, Wqkvh + DM * DM, Wqkvl + DM * DM, DM, DM);
    wconv_k<<<dim3(DM / 32, DM / 32), cb>>>(Wv, Wqkvh + 2 * DM * DM, Wqkvl + 2 * DM * DM, DM, DM);
    biascat_k<<<12, 256>>>(bq, bk, bv, bqkv);
    ln_k<<<TOKENS, 256>>>(src, g1, be1, Xh, Xl);

    // launch 5: fused QKV (N=3072) — profiled by ncu
    hgemm<3, 256><<<dim3(3 * DM / 256, TOKENS / 128), 256, SMEM_256>>>(
        Xh, Xl, Wqkvh, Wqkvl, bqkv, nullptr, Qb, Kb, Vb, nullptr, nullptr, TOKENS, 3 * DM, DM);

    // attention -> CTX bf16 pair
    attn_k<<<dim3(16, 128), 256, ATTN_SMEM>>>(Qb, Kb, Vb, Chb, Clb);

    // Wo + residual(src) -> S2 fp32
    wconv_k<<<dim3(DM / 32, DM / 32), cb>>>(Wo, Woh, Wol, DM, DM);
    hgemm<2, 128><<<dim3(DM / 128, TOKENS / 128), 256, SMEM_128>>>(
        Chb, Clb, Woh, Wol, bo, src, S2, nullptr, nullptr, nullptr, nullptr, TOKENS, DM, DM);

    // LN2 -> Y bf16 pair
    ln_k<<<TOKENS, 256>>>(S2, g2, be2, Yh, Yl);

    // W1 + relu -> H bf16 pair
    wconv_k<<<dim3(DFF / 32, DM / 32), cb>>>(W1, W1h, W1l, DM, DFF);
    hgemm<1, 256><<<dim3(DFF / 256, TOKENS / 128), 256, SMEM_256>>>(
        Yh, Yl, W1h, W1l, b1, nullptr, nullptr, nullptr, nullptr, Hh, Hl, TOKENS, DFF, DM);

    // W2 + residual(S2) -> out fp32
    wconv_k<<<dim3(DM / 32, DFF / 32), cb>>>(W2, W2h, W2l, DFF, DM);
    hgemm<2, 128><<<dim3(DM / 128, TOKENS / 128), 256, SMEM_128>>>(
        Hh, Hl, W2h, W2l, b2, S2, out, nullptr, nullptr, nullptr, nullptr, TOKENS, DM, DFF);
}

// round 7
// speedup vs baseline: 2.0129x; 1.0232x over previous
#include <cuda_runtime.h>
#include <cuda_bf16.h>
#include <cstdint>

#define TOKENS 8192
#define DM 1024
#define DFF 4096
#define NHEAD 16
#define DHEAD 64

// ---------------- scratch (device globals; no runtime alloc allowed) ----------------
__device__ __nv_bfloat16 g_Xh[TOKENS * DM], g_Xl[TOKENS * DM];
__device__ __nv_bfloat16 g_Yh[TOKENS * DM], g_Yl[TOKENS * DM];
__device__ __nv_bfloat16 g_Ch[TOKENS * DM], g_Cl[TOKENS * DM];
__device__ __nv_bfloat16 g_Hh[(size_t)TOKENS * DFF], g_Hl[(size_t)TOKENS * DFF];
__device__ float g_Q[TOKENS * DM];
__device__ float g_K[TOKENS * DM];
__device__ float g_V[TOKENS * DM];
__device__ float g_S2[TOKENS * DM];
__device__ float g_bqkv[3 * DM];
// transposed + split weights: [N, K] bf16
__device__ __nv_bfloat16 g_Wqkvh[3 * DM * DM], g_Wqkvl[3 * DM * DM];
__device__ __nv_bfloat16 g_Woh[DM * DM], g_Wol[DM * DM];
__device__ __nv_bfloat16 g_W1h[(size_t)DM * DFF], g_W1l[(size_t)DM * DFF];
__device__ __nv_bfloat16 g_W2h[(size_t)DM * DFF], g_W2l[(size_t)DM * DFF];

// ---------------- PTX helpers ----------------
__device__ __forceinline__ uint32_t smem_u32(const void* p) {
    uint32_t a;
    asm("{ .reg .u64 t; cvta.to.shared.u64 t, %1; cvt.u32.u64 %0, t; }" : "=r"(a) : "l"(p));
    return a;
}
__device__ __forceinline__ void cpa16(uint32_t s, const void* g) {
    asm volatile("cp.async.cg.shared.global [%0], [%1], 16;" :: "r"(s), "l"(g));
}
__device__ __forceinline__ void ldm4(uint32_t* r, uint32_t addr) {
    asm volatile("ldmatrix.sync.aligned.m8n8.x4.shared.b16 {%0,%1,%2,%3}, [%4];"
                 : "=r"(r[0]), "=r"(r[1]), "=r"(r[2]), "=r"(r[3])
                 : "r"(addr));
}
__device__ __forceinline__ void mma_bf16(float* c, const uint32_t* a, const uint32_t* b) {
    asm volatile(
        "mma.sync.aligned.m16n8k16.row.col.f32.bf16.bf16.f32 "
        "{%0,%1,%2,%3}, {%4,%5,%6,%7}, {%8,%9}, {%0,%1,%2,%3};"
        : "+f"(c[0]), "+f"(c[1]), "+f"(c[2]), "+f"(c[3])
        : "r"(a[0]), "r"(a[1]), "r"(a[2]), "r"(a[3]), "r"(b[0]), "r"(b[1]));
}
__device__ __forceinline__ void split_bf16(float v, __nv_bfloat16& h, __nv_bfloat16& l) {
    h = __float2bfloat16(v);
    l = __float2bfloat16(v - __bfloat162float(h));
}

// ------- fused QKV weight transpose+split + bias concat (ONE launch) -------
__global__ void __launch_bounds__(256) wconv3_k(const float* __restrict__ Wq,
                                                const float* __restrict__ Wk,
                                                const float* __restrict__ Wv,
                                                const float* __restrict__ bq,
                                                const float* __restrict__ bk,
                                                const float* __restrict__ bv,
                                                __nv_bfloat16* __restrict__ Th,
                                                __nv_bfloat16* __restrict__ Tl,
                                                float* __restrict__ bqkv) {
    const int z = blockIdx.z;
    const float* W = (z == 0) ? Wq : (z == 1) ? Wk : Wv;
    const float* bi = (z == 0) ? bq : (z == 1) ? bk : bv;
    __nv_bfloat16* Tz = Th + (size_t)z * DM * DM;
    __nv_bfloat16* Tzl = Tl + (size_t)z * DM * DM;

    __shared__ float t[32][33];
    const int bx = blockIdx.x * 32;  // N
    const int by = blockIdx.y * 32;  // K
    const int x = threadIdx.x;
    const int y0 = threadIdx.y;
#pragma unroll
    for (int dy = 0; dy < 32; dy += 8)
        t[y0 + dy][x] = W[(size_t)(by + y0 + dy) * DM + bx + x];
    __syncthreads();
#pragma unroll
    for (int dy = 0; dy < 32; dy += 8) {
        const float v = t[x][y0 + dy];
        __nv_bfloat16 h, l;
        split_bf16(v, h, l);
        const size_t o = (size_t)(bx + y0 + dy) * DM + by + x;
        Tz[o] = h;
        Tzl[o] = l;
    }
    if (blockIdx.y == 0 && y0 == 0) bqkv[z * DM + bx + x] = bi[bx + x];
}

// ---------------- generic weight transpose + split ----------------
__global__ void __launch_bounds__(256) wconv_k(const float* __restrict__ W,
                                               __nv_bfloat16* __restrict__ Th,
                                               __nv_bfloat16* __restrict__ Tl,
                                               int K, int N) {
    __shared__ float t[32][33];
    const int bx = blockIdx.x * 32;
    const int by = blockIdx.y * 32;
    const int x = threadIdx.x;
    const int y0 = threadIdx.y;
#pragma unroll
    for (int dy = 0; dy < 32; dy += 8)
        t[y0 + dy][x] = W[(size_t)(by + y0 + dy) * N + bx + x];
    __syncthreads();
#pragma unroll
    for (int dy = 0; dy < 32; dy += 8) {
        const float v = t[x][y0 + dy];
        __nv_bfloat16 h, l;
        split_bf16(v, h, l);
        const size_t o = (size_t)(bx + y0 + dy) * K + by + x;
        Th[o] = h;
        Tl[o] = l;
    }
}

// ---------------- LayerNorm: writes bf16 hi/lo ----------------
__global__ void __launch_bounds__(256) ln_k(const float* __restrict__ x,
                                            const float* __restrict__ g,
                                            const float* __restrict__ be,
                                            __nv_bfloat16* __restrict__ yh,
                                            __nv_bfloat16* __restrict__ yl) {
    const int row = blockIdx.x;
    const int t = threadIdx.x;
    const size_t base = (size_t)row * DM;
    const float4 v = *(const float4*)(x + base + t * 4);
    float s = v.x + v.y + v.z + v.w;
    float q = v.x * v.x + v.y * v.y + v.z * v.z + v.w * v.w;
#pragma unroll
    for (int off = 16; off; off >>= 1) {
        s += __shfl_xor_sync(0xffffffffu, s, off);
        q += __shfl_xor_sync(0xffffffffu, q, off);
    }
    __shared__ float rs[8], rq[8];
    if ((t & 31) == 0) { rs[t >> 5] = s; rq[t >> 5] = q; }
    __syncthreads();
    s = 0.f; q = 0.f;
#pragma unroll
    for (int i = 0; i < 8; ++i) { s += rs[i]; q += rq[i]; }
    const float mu = s * (1.0f / DM);
    const float var = q * (1.0f / DM) - mu * mu;
    const float r = rsqrtf(var + 1e-5f);
    const float4 gv = *(const float4*)(g + t * 4);
    const float4 bv = *(const float4*)(be + t * 4);
    float yv[4];
    yv[0] = (v.x - mu) * r * gv.x + bv.x;
    yv[1] = (v.y - mu) * r * gv.y + bv.y;
    yv[2] = (v.z - mu) * r * gv.z + bv.z;
    yv[3] = (v.w - mu) * r * gv.w + bv.w;
    __nv_bfloat16 h[4], l[4];
#pragma unroll
    for (int i = 0; i < 4; ++i) split_bf16(yv[i], h[i], l[i]);
    __nv_bfloat162 h01, h23, l01, l23;
    h01.x = h[0]; h01.y = h[1]; h23.x = h[2]; h23.y = h[3];
    l01.x = l[0]; l01.y = l[1]; l23.x = l[2]; l23.y = l[3];
    *(__nv_bfloat162*)(yh + base + t * 4) = h01;
    *(__nv_bfloat162*)(yh + base + t * 4 + 2) = h23;
    *(__nv_bfloat162*)(yl + base + t * 4) = l01;
    *(__nv_bfloat162*)(yl + base + t * 4 + 2) = l23;
}

// ---------------- split-bf16 HMMA GEMM ----------------
// C[M,N] = A[M,K] @ B[N,K]^T.  tile 128 x BN_, BK=32, 8 warps (2x4), NST-stage cp.async,
// one __syncthreads per iteration, tail-exact wait_group.
// EPI: 1 relu->bf16 pair, 2 +res->fp32, 3 fused-QKV scatter fp32
#define HBK 32
#define SROW 80
#define A_BYTES 10240  // 128 * 80

template <int EPI, int BN_, int NST>
__global__ void __launch_bounds__(256, 1)
hgemm(const __nv_bfloat16* __restrict__ Ah, const __nv_bfloat16* __restrict__ Al,
      const __nv_bfloat16* __restrict__ Bh, const __nv_bfloat16* __restrict__ Bl,
      const float* __restrict__ bias, const float* __restrict__ res,
      float* __restrict__ Cf, float* __restrict__ Cf2, float* __restrict__ Cf3,
      __nv_bfloat16* __restrict__ Ch, __nv_bfloat16* __restrict__ Cl,
      int M, int N, int K) {
    constexpr int WT_N = BN_ / 4;
    constexpr int NG = WT_N / 16;
    constexpr int NI = WT_N / 8;
    constexpr int B_BYTES = BN_ * SROW;
    constexpr int STAGE_B = 2 * A_BYTES + 2 * B_BYTES;

    extern __shared__ char sm[];
    const uint32_t smb = smem_u32(sm);
    const int tid = threadIdx.x;
    const int wid = tid >> 5;
    const int lane = tid & 31;
    const int wm = wid & 1;
    const int wn = wid >> 1;
    const int bm = blockIdx.y * 128;
    const int bn = blockIdx.x * BN_;
    const int nch = K / HBK;

    auto load_stage = [&](int chunk, int s) {
        const int k0 = chunk * HBK;
        const uint32_t base = smb + s * STAGE_B;
        constexpr int ITER = (128 + BN_) * 4 / 256;
#pragma unroll
        for (int it = 0; it < ITER; ++it) {
            const int idx = tid + (it << 8);
            const int r = idx >> 2, c4 = idx & 3;
            if (r < 128) {
                const uint32_t dst = base + r * SROW + c4 * 16;
                const size_t go = ((size_t)(bm + r) * K + k0 + c4 * 8) * 2;
                cpa16(dst, (const char*)Ah + go);
                cpa16(dst + A_BYTES, (const char*)Al + go);
            } else {
                const int rb = r - 128;
                const uint32_t dst = base + 2 * A_BYTES + rb * SROW + c4 * 16;
                const size_t go = ((size_t)(bn + rb) * K + k0 + c4 * 8) * 2;
                cpa16(dst, (const char*)Bh + go);
                cpa16(dst + B_BYTES, (const char*)Bl + go);
            }
        }
        asm volatile("cp.async.commit_group;");
    };

    float acc[4][NI][4];
#pragma unroll
    for (int a = 0; a < 4; ++a)
#pragma unroll
        for (int b = 0; b < NI; ++b)
#pragma unroll
            for (int c = 0; c < 4; ++c) acc[a][b][c] = 0.f;

    // prologue: fill NST-1 stages
#pragma unroll
    for (int s = 0; s < NST - 1; ++s)
        if (s < nch) load_stage(s, s);

    const uint32_t a_row = (lane & 15);
    const uint32_t a_koff = ((lane >> 4) << 3);
    const uint32_t b_row = (lane & 7) + (((lane >> 4) & 1) << 3);
    const uint32_t b_koff = (((lane >> 3) & 1) << 3);

    for (int i = 0; i < nch; ++i) {
        // ensure group i complete (tail-exact)
        if (i + NST - 1 <= nch) {
            asm volatile("cp.async.wait_group %0;" :: "n"(NST - 2));
        } else {
            asm volatile("cp.async.wait_group 0;");
        }
        __syncthreads();
        if (i + NST - 1 < nch) load_stage(i + NST - 1, (i + NST - 1) % NST);

        const uint32_t sb = smb + (i % NST) * STAGE_B;
#pragma unroll
        for (int ks = 0; ks < 2; ++ks) {
            const int k0 = ks * 16;
            uint32_t afh[4][4], afl[4][4];
#pragma unroll
            for (int mi = 0; mi < 4; ++mi) {
                const uint32_t addr =
                    sb + (wm * 64 + mi * 16 + a_row) * SROW + (k0 + a_koff) * 2;
                ldm4(afh[mi], addr);
                ldm4(afl[mi], addr + A_BYTES);
            }
            uint32_t bfh[NG][4], bfl[NG][4];
#pragma unroll
            for (int g = 0; g < NG; ++g) {
                const uint32_t addr =
                    sb + 2 * A_BYTES + (wn * WT_N + g * 16 + b_row) * SROW + (k0 + b_koff) * 2;
                ldm4(bfh[g], addr);
                ldm4(bfl[g], addr + B_BYTES);
            }
#pragma unroll
            for (int mi = 0; mi < 4; ++mi)
#pragma unroll
                for (int ni = 0; ni < NI; ++ni) {
                    const int g = ni >> 1;
                    const int hf = (ni & 1) * 2;
                    mma_bf16(acc[mi][ni], afh[mi], &bfh[g][hf]);
                    mma_bf16(acc[mi][ni], afh[mi], &bfl[g][hf]);
                    mma_bf16(acc[mi][ni], afl[mi], &bfh[g][hf]);
                }
        }
    }

    // epilogue
    const int er = lane >> 2;
    const int ec = (lane & 3) * 2;
#pragma unroll
    for (int mi = 0; mi < 4; ++mi)
#pragma unroll
        for (int ni = 0; ni < NI; ++ni) {
#pragma unroll
            for (int half = 0; half < 2; ++half) {
                const int row = bm + wm * 64 + mi * 16 + er + half * 8;
                const int col = bn + wn * WT_N + ni * 8 + ec;
                float v0 = acc[mi][ni][half * 2 + 0] + bias[col];
                float v1 = acc[mi][ni][half * 2 + 1] + bias[col + 1];
                if (EPI == 1) {
                    v0 = fmaxf(v0, 0.f);
                    v1 = fmaxf(v1, 0.f);
                    __nv_bfloat16 h0, l0, h1, l1;
                    split_bf16(v0, h0, l0);
                    split_bf16(v1, h1, l1);
                    const size_t o = (size_t)row * N + col;
                    __nv_bfloat162 hp, lp;
                    hp.x = h0; hp.y = h1;
                    lp.x = l0; lp.y = l1;
                    *(__nv_bfloat162*)(Ch + o) = hp;
                    *(__nv_bfloat162*)(Cl + o) = lp;
                } else if (EPI == 2) {
                    const size_t o = (size_t)row * N + col;
                    const float2 rv = *(const float2*)(res + o);
                    float2 ov;
                    ov.x = v0 + rv.x;
                    ov.y = v1 + rv.y;
                    *(float2*)(Cf + o) = ov;
                } else {
                    const int t = col >> 10;
                    const int cc = col & 1023;
                    const int b = row >> 10, s = row & 1023;
                    const int h = cc >> 6, d = cc & 63;
                    float* dst = (t == 0) ? Cf : (t == 1) ? Cf2 : Cf3;
                    float2 ov;
                    ov.x = v0;
                    ov.y = v1;
                    *(float2*)(dst + (((size_t)(b * NHEAD + h) << 10) + s) * DHEAD + d) = ov;
                }
            }
        }
}

// ---------------- Flash attention, fp32, 64x64 tiles ----------------
__global__ void __launch_bounds__(256) attn_k(const float* __restrict__ Q,
                                              const float* __restrict__ Kg,
                                              const float* __restrict__ Vg,
                                              __nv_bfloat16* __restrict__ CTXh,
                                              __nv_bfloat16* __restrict__ CTXl) {
    extern __shared__ float smf[];
    float* Qs = smf;
    float* Ks = smf + 4352;
    float* Ps = smf + 8704;
    float* Vs = smf + 13056;

    const int tid = threadIdx.x;
    const int ty = tid >> 4;
    const int tx = tid & 15;
    const int bh = blockIdx.y;
    const int q0 = blockIdx.x << 6;
    const size_t base = (size_t)bh << 16;

    const int lrow = tid >> 4;
    const int ld4 = (tid & 15) << 2;

#pragma unroll
    for (int it = 0; it < 4; ++it) {
        const int s = lrow + (it << 4);
        const float4 v = *(const float4*)(Q + base + (size_t)(q0 + s) * DHEAD + ld4);
        Qs[(ld4 + 0) * 68 + s] = v.x;
        Qs[(ld4 + 1) * 68 + s] = v.y;
        Qs[(ld4 + 2) * 68 + s] = v.z;
        Qs[(ld4 + 3) * 68 + s] = v.w;
    }

    float m[4], l[4];
    float4 o[4];
#pragma unroll
    for (int i = 0; i < 4; ++i) {
        m[i] = -1e30f;
        l[i] = 0.0f;
        o[i] = make_float4(0.f, 0.f, 0.f, 0.f);
    }

    for (int kt = 0; kt < 16; ++kt) {
        __syncthreads();
        const float* Kt = Kg + base + ((size_t)(kt << 6)) * DHEAD;
        const float* Vt = Vg + base + ((size_t)(kt << 6)) * DHEAD;
#pragma unroll
        for (int it = 0; it < 4; ++it) {
            const int s = lrow + (it << 4);
            const float4 kv = *(const float4*)(Kt + s * DHEAD + ld4);
            Ks[(ld4 + 0) * 68 + s] = kv.x;
            Ks[(ld4 + 1) * 68 + s] = kv.y;
            Ks[(ld4 + 2) * 68 + s] = kv.z;
            Ks[(ld4 + 3) * 68 + s] = kv.w;
            *(float4*)&Vs[s * 64 + ld4] = *(const float4*)(Vt + s * DHEAD + ld4);
        }
        __syncthreads();

        float s4[4][4];
#pragma unroll
        for (int i = 0; i < 4; ++i)
#pragma unroll
            for (int c = 0; c < 4; ++c) s4[i][c] = 0.f;
#pragma unroll 8
        for (int kk = 0; kk < 64; ++kk) {
            const float4 qf = *(const float4*)&Qs[kk * 68 + (ty << 2)];
            const float4 kf = *(const float4*)&Ks[kk * 68 + (tx << 2)];
            const float qa[4] = {qf.x, qf.y, qf.z, qf.w};
            const float kb[4] = {kf.x, kf.y, kf.z, kf.w};
#pragma unroll
            for (int i = 0; i < 4; ++i)
#pragma unroll
                for (int c = 0; c < 4; ++c) s4[i][c] += qa[i] * kb[c];
        }

#pragma unroll
        for (int i = 0; i < 4; ++i) {
#pragma unroll
            for (int c = 0; c < 4; ++c) s4[i][c] *= 0.125f;
            float tm = fmaxf(fmaxf(s4[i][0], s4[i][1]), fmaxf(s4[i][2], s4[i][3]));
#pragma unroll
            for (int off = 8; off; off >>= 1)
                tm = fmaxf(tm, __shfl_xor_sync(0xffffffffu, tm, off));
            const float mn = fmaxf(m[i], tm);
            const float corr = __expf(m[i] - mn);
            float rsum = 0.f;
#pragma unroll
            for (int c = 0; c < 4; ++c) {
                const float p = __expf(s4[i][c] - mn);
                s4[i][c] = p;
                rsum += p;
            }
#pragma unroll
            for (int off = 8; off; off >>= 1)
                rsum += __shfl_xor_sync(0xffffffffu, rsum, off);
            l[i] = l[i] * corr + rsum;
            o[i].x *= corr; o[i].y *= corr; o[i].z *= corr; o[i].w *= corr;
            m[i] = mn;
#pragma unroll
            for (int c = 0; c < 4; ++c)
                Ps[((tx << 2) + c) * 68 + (ty << 2) + i] = s4[i][c];
        }
        __syncthreads();

#pragma unroll 8
        for (int kk = 0; kk < 64; ++kk) {
            const float4 pf = *(const float4*)&Ps[kk * 68 + (ty << 2)];
            const float4 vf = *(const float4*)&Vs[kk * 64 + (tx << 2)];
            o[0].x += pf.x * vf.x; o[0].y += pf.x * vf.y; o[0].z += pf.x * vf.z; o[0].w += pf.x * vf.w;
            o[1].x += pf.y * vf.x; o[1].y += pf.y * vf.y; o[1].z += pf.y * vf.z; o[1].w += pf.y * vf.w;
            o[2].x += pf.z * vf.x; o[2].y += pf.z * vf.y; o[2].z += pf.z * vf.z; o[2].w += pf.z * vf.w;
            o[3].x += pf.w * vf.x; o[3].y += pf.w * vf.y; o[3].z += pf.w * vf.z; o[3].w += pf.w * vf.w;
        }
    }

    const int b = bh >> 4, h = bh & 15;
#pragma unroll
    for (int i = 0; i < 4; ++i) {
        const float inv = 1.0f / l[i];
        float rv[4] = {o[i].x * inv, o[i].y * inv, o[i].z * inv, o[i].w * inv};
        const size_t off = ((size_t)(b * 1024 + q0 + (ty << 2) + i)) * DM + h * DHEAD + (tx << 2);
        __nv_bfloat16 hh[4], ll[4];
#pragma unroll
        for (int c = 0; c < 4; ++c) split_bf16(rv[c], hh[c], ll[c]);
        __nv_bfloat162 a, bq, c2, d2;
        a.x = hh[0]; a.y = hh[1]; bq.x = hh[2]; bq.y = hh[3];
        c2.x = ll[0]; c2.y = ll[1]; d2.x = ll[2]; d2.y = ll[3];
        *(__nv_bfloat162*)(CTXh + off) = a;
        *(__nv_bfloat162*)(CTXh + off + 2) = bq;
        *(__nv_bfloat162*)(CTXl + off) = c2;
        *(__nv_bfloat162*)(CTXl + off + 2) = d2;
    }
}

// ---------------- launch ----------------
extern "C" void kernel_launch(void* const* d_in, const int* in_sizes, int n_in,
                              void* d_out, int out_size) {
    const float* src = (const float*)d_in[0];
    const float* Wq = (const float*)d_in[1];
    const float* bq = (const float*)d_in[2];
    const float* Wk = (const float*)d_in[3];
    const float* bk = (const float*)d_in[4];
    const float* Wv = (const float*)d_in[5];
    const float* bv = (const float*)d_in[6];
    const float* Wo = (const float*)d_in[7];
    const float* bo = (const float*)d_in[8];
    const float* W1 = (const float*)d_in[9];
    const float* b1 = (const float*)d_in[10];
    const float* W2 = (const float*)d_in[11];
    const float* b2 = (const float*)d_in[12];
    const float* g1 = (const float*)d_in[13];
    const float* be1 = (const float*)d_in[14];
    const float* g2 = (const float*)d_in[15];
    const float* be2 = (const float*)d_in[16];
    float* out = (float*)d_out;

#define SYM(p, s) cudaGetSymbolAddress((void**)&p, s)
    __nv_bfloat16 *Xh, *Xl, *Yh, *Yl, *Chb, *Clb, *Hh, *Hl;
    __nv_bfloat16 *Wqkvh, *Wqkvl, *Woh, *Wol, *W1h, *W1l, *W2h, *W2l;
    float *Qb, *Kb, *Vb, *S2, *bqkv;
    SYM(Xh, g_Xh); SYM(Xl, g_Xl); SYM(Yh, g_Yh); SYM(Yl, g_Yl);
    SYM(Chb, g_Ch); SYM(Clb, g_Cl); SYM(Hh, g_Hh); SYM(Hl, g_Hl);
    SYM(Qb, g_Q); SYM(Kb, g_K); SYM(Vb, g_V); SYM(S2, g_S2); SYM(bqkv, g_bqkv);
    SYM(Wqkvh, g_Wqkvh); SYM(Wqkvl, g_Wqkvl);
    SYM(Woh, g_Woh); SYM(Wol, g_Wol);
    SYM(W1h, g_W1h); SYM(W1l, g_W1l); SYM(W2h, g_W2h); SYM(W2l, g_W2l);
#undef SYM

    const int ATTN_SMEM = 68608;
    const int SMEM_256 = 3 * (2 * A_BYTES + 2 * 256 * SROW);  // 184320
    const int SMEM_128 = 5 * (2 * A_BYTES + 2 * 128 * SROW);  // 204800
    cudaFuncSetAttribute(attn_k, cudaFuncAttributeMaxDynamicSharedMemorySize, ATTN_SMEM);
    cudaFuncSetAttribute(hgemm<3, 256, 3>, cudaFuncAttributeMaxDynamicSharedMemorySize, SMEM_256);
    cudaFuncSetAttribute(hgemm<1, 256, 3>, cudaFuncAttributeMaxDynamicSharedMemorySize, SMEM_256);
    cudaFuncSetAttribute(hgemm<2, 128, 5>, cudaFuncAttributeMaxDynamicSharedMemorySize, SMEM_128);

    dim3 cb(32, 8);
    // kernel 1: fused QKV weight conv + bias concat
    wconv3_k<<<dim3(DM / 32, DM / 32, 3), cb>>>(Wq, Wk, Wv, bq, bk, bv, Wqkvh, Wqkvl, bqkv);
    // kernel 2: LN1
    ln_k<<<TOKENS, 256>>>(src, g1, be1, Xh, Xl);
    // kernel 3: Wo conv (hoisted here so kernel 4 is the profiled hgemm)
    wconv_k<<<dim3(DM / 32, DM / 32), cb>>>(Wo, Woh, Wol, DM, DM);

    // kernel 4: fused QKV GEMM (N=3072) — ncu -s 5 lands here (2 memsets + 3 kernels)
    hgemm<3, 256, 3><<<dim3(3 * DM / 256, TOKENS / 128), 256, SMEM_256>>>(
        Xh, Xl, Wqkvh, Wqkvl, bqkv, nullptr, Qb, Kb, Vb, nullptr, nullptr, TOKENS, 3 * DM, DM);

    // attention -> CTX bf16 pair
    attn_k<<<dim3(16, 128), 256, ATTN_SMEM>>>(Qb, Kb, Vb, Chb, Clb);

    // Wo + residual(src) -> S2 fp32
    hgemm<2, 128, 5><<<dim3(DM / 128, TOKENS / 128), 256, SMEM_128>>>(
        Chb, Clb, Woh, Wol, bo, src, S2, nullptr, nullptr, nullptr, nullptr, TOKENS, DM, DM);

    // LN2 -> Y bf16 pair
    ln_k<<<TOKENS, 256>>>(S2, g2, be2, Yh, Yl);

    // W1 + relu -> H bf16 pair
    wconv_k<<<dim3(DFF / 32, DM / 32), cb>>>(W1, W1h, W1l, DM, DFF);
    hgemm<1, 256, 3><<<dim3(DFF / 256, TOKENS / 128), 256, SMEM_256>>>(
        Yh, Yl, W1h, W1l, b1, nullptr, nullptr, nullptr, nullptr, Hh, Hl, TOKENS, DFF, DM);

    // W2 + residual(S2) -> out fp32
    wconv_k<<<dim3(DM / 32, DFF / 32), cb>>>(W2, W2h, W2l, DFF, DM);
    hgemm<2, 128, 5><<<dim3(DM / 128, TOKENS / 128), 256, SMEM_128>>>(
        Hh, Hl, W2h, W2l, b2, S2, out, nullptr, nullptr, nullptr, nullptr, TOKENS, DM, DFF);
}

// round 8
// speedup vs baseline: 2.0513x; 1.0191x over previous
#include <cuda_runtime.h>
#include <cuda_bf16.h>
#include <cstdint>

#define TOKENS 8192
#define DM 1024
#define DFF 4096
#define NHEAD 16
#define DHEAD 64

// ---------------- scratch (device globals; no runtime alloc allowed) ----------------
__device__ __nv_bfloat16 g_Xh[TOKENS * DM], g_Xl[TOKENS * DM];
__device__ __nv_bfloat16 g_Yh[TOKENS * DM], g_Yl[TOKENS * DM];
__device__ __nv_bfloat16 g_Ch[TOKENS * DM], g_Cl[TOKENS * DM];
__device__ __nv_bfloat16 g_Hh[(size_t)TOKENS * DFF], g_Hl[(size_t)TOKENS * DFF];
__device__ float g_Q[TOKENS * DM];
__device__ float g_K[TOKENS * DM];
__device__ float g_V[TOKENS * DM];
__device__ float g_S2[TOKENS * DM];
__device__ float g_bqkv[3 * DM];
// transposed + split weights: [N, K] bf16
__device__ __nv_bfloat16 g_Wqkvh[3 * DM * DM], g_Wqkvl[3 * DM * DM];
__device__ __nv_bfloat16 g_Woh[DM * DM], g_Wol[DM * DM];
__device__ __nv_bfloat16 g_W1h[(size_t)DM * DFF], g_W1l[(size_t)DM * DFF];
__device__ __nv_bfloat16 g_W2h[(size_t)DM * DFF], g_W2l[(size_t)DM * DFF];

// ---------------- PTX helpers ----------------
__device__ __forceinline__ uint32_t smem_u32(const void* p) {
    uint32_t a;
    asm("{ .reg .u64 t; cvta.to.shared.u64 t, %1; cvt.u32.u64 %0, t; }" : "=r"(a) : "l"(p));
    return a;
}
__device__ __forceinline__ void cpa16(uint32_t s, const void* g) {
    asm volatile("cp.async.cg.shared.global [%0], [%1], 16;" :: "r"(s), "l"(g));
}
__device__ __forceinline__ void ldm4(uint32_t* r, uint32_t addr) {
    asm volatile("ldmatrix.sync.aligned.m8n8.x4.shared.b16 {%0,%1,%2,%3}, [%4];"
                 : "=r"(r[0]), "=r"(r[1]), "=r"(r[2]), "=r"(r[3])
                 : "r"(addr));
}
__device__ __forceinline__ void mma_bf16(float* c, const uint32_t* a, const uint32_t* b) {
    asm volatile(
        "mma.sync.aligned.m16n8k16.row.col.f32.bf16.bf16.f32 "
        "{%0,%1,%2,%3}, {%4,%5,%6,%7}, {%8,%9}, {%0,%1,%2,%3};"
        : "+f"(c[0]), "+f"(c[1]), "+f"(c[2]), "+f"(c[3])
        : "r"(a[0]), "r"(a[1]), "r"(a[2]), "r"(a[3]), "r"(b[0]), "r"(b[1]));
}
__device__ __forceinline__ void split_bf16(float v, __nv_bfloat16& h, __nv_bfloat16& l) {
    h = __float2bfloat16(v);
    l = __float2bfloat16(v - __bfloat162float(h));
}

// ------- fused QKV weight transpose+split + bias concat (ONE launch) -------
__global__ void __launch_bounds__(256) wconv3_k(const float* __restrict__ Wq,
                                                const float* __restrict__ Wk,
                                                const float* __restrict__ Wv,
                                                const float* __restrict__ bq,
                                                const float* __restrict__ bk,
                                                const float* __restrict__ bv,
                                                __nv_bfloat16* __restrict__ Th,
                                                __nv_bfloat16* __restrict__ Tl,
                                                float* __restrict__ bqkv) {
    const int z = blockIdx.z;
    const float* W = (z == 0) ? Wq : (z == 1) ? Wk : Wv;
    const float* bi = (z == 0) ? bq : (z == 1) ? bk : bv;
    __nv_bfloat16* Tz = Th + (size_t)z * DM * DM;
    __nv_bfloat16* Tzl = Tl + (size_t)z * DM * DM;

    __shared__ float t[32][33];
    const int bx = blockIdx.x * 32;
    const int by = blockIdx.y * 32;
    const int x = threadIdx.x;
    const int y0 = threadIdx.y;
#pragma unroll
    for (int dy = 0; dy < 32; dy += 8)
        t[y0 + dy][x] = W[(size_t)(by + y0 + dy) * DM + bx + x];
    __syncthreads();
#pragma unroll
    for (int dy = 0; dy < 32; dy += 8) {
        const float v = t[x][y0 + dy];
        __nv_bfloat16 h, l;
        split_bf16(v, h, l);
        const size_t o = (size_t)(bx + y0 + dy) * DM + by + x;
        Tz[o] = h;
        Tzl[o] = l;
    }
    if (blockIdx.y == 0 && y0 == 0) bqkv[z * DM + bx + x] = bi[bx + x];
}

// ---------------- generic weight transpose + split ----------------
__global__ void __launch_bounds__(256) wconv_k(const float* __restrict__ W,
                                               __nv_bfloat16* __restrict__ Th,
                                               __nv_bfloat16* __restrict__ Tl,
                                               int K, int N) {
    __shared__ float t[32][33];
    const int bx = blockIdx.x * 32;
    const int by = blockIdx.y * 32;
    const int x = threadIdx.x;
    const int y0 = threadIdx.y;
#pragma unroll
    for (int dy = 0; dy < 32; dy += 8)
        t[y0 + dy][x] = W[(size_t)(by + y0 + dy) * N + bx + x];
    __syncthreads();
#pragma unroll
    for (int dy = 0; dy < 32; dy += 8) {
        const float v = t[x][y0 + dy];
        __nv_bfloat16 h, l;
        split_bf16(v, h, l);
        const size_t o = (size_t)(bx + y0 + dy) * K + by + x;
        Th[o] = h;
        Tl[o] = l;
    }
}

// ---------------- LayerNorm: writes bf16 hi/lo ----------------
__global__ void __launch_bounds__(256) ln_k(const float* __restrict__ x,
                                            const float* __restrict__ g,
                                            const float* __restrict__ be,
                                            __nv_bfloat16* __restrict__ yh,
                                            __nv_bfloat16* __restrict__ yl) {
    const int row = blockIdx.x;
    const int t = threadIdx.x;
    const size_t base = (size_t)row * DM;
    const float4 v = *(const float4*)(x + base + t * 4);
    float s = v.x + v.y + v.z + v.w;
    float q = v.x * v.x + v.y * v.y + v.z * v.z + v.w * v.w;
#pragma unroll
    for (int off = 16; off; off >>= 1) {
        s += __shfl_xor_sync(0xffffffffu, s, off);
        q += __shfl_xor_sync(0xffffffffu, q, off);
    }
    __shared__ float rs[8], rq[8];
    if ((t & 31) == 0) { rs[t >> 5] = s; rq[t >> 5] = q; }
    __syncthreads();
    s = 0.f; q = 0.f;
#pragma unroll
    for (int i = 0; i < 8; ++i) { s += rs[i]; q += rq[i]; }
    const float mu = s * (1.0f / DM);
    const float var = q * (1.0f / DM) - mu * mu;
    const float r = rsqrtf(var + 1e-5f);
    const float4 gv = *(const float4*)(g + t * 4);
    const float4 bv = *(const float4*)(be + t * 4);
    float yv[4];
    yv[0] = (v.x - mu) * r * gv.x + bv.x;
    yv[1] = (v.y - mu) * r * gv.y + bv.y;
    yv[2] = (v.z - mu) * r * gv.z + bv.z;
    yv[3] = (v.w - mu) * r * gv.w + bv.w;
    __nv_bfloat16 h[4], l[4];
#pragma unroll
    for (int i = 0; i < 4; ++i) split_bf16(yv[i], h[i], l[i]);
    __nv_bfloat162 h01, h23, l01, l23;
    h01.x = h[0]; h01.y = h[1]; h23.x = h[2]; h23.y = h[3];
    l01.x = l[0]; l01.y = l[1]; l23.x = l[2]; l23.y = l[3];
    *(__nv_bfloat162*)(yh + base + t * 4) = h01;
    *(__nv_bfloat162*)(yh + base + t * 4 + 2) = h23;
    *(__nv_bfloat162*)(yl + base + t * 4) = l01;
    *(__nv_bfloat162*)(yl + base + t * 4 + 2) = l23;
}

// ---------------- split-bf16 HMMA GEMM, 512 threads, tile 128x256 ----------------
// C[M,N] = A[M,K] @ B[N,K]^T.  16 warps (2x8), warp tile 64x32, BK=32, 3-stage cp.async.
// EPI: 1 relu->bf16 pair, 2 +res->fp32, 3 fused-QKV scatter fp32
#define HBK 32
#define SROW 80
#define A_BYTES 10240   // 128 * 80
#define B_BYTES 20480   // 256 * 80
#define STAGE_B (2 * A_BYTES + 2 * B_BYTES)  // 61440
#define NST 3
#define SMEM_G (NST * STAGE_B)  // 184320

template <int EPI>
__global__ void __launch_bounds__(512, 1)
hgemm(const __nv_bfloat16* __restrict__ Ah, const __nv_bfloat16* __restrict__ Al,
      const __nv_bfloat16* __restrict__ Bh, const __nv_bfloat16* __restrict__ Bl,
      const float* __restrict__ bias, const float* __restrict__ res,
      float* __restrict__ Cf, float* __restrict__ Cf2, float* __restrict__ Cf3,
      __nv_bfloat16* __restrict__ Ch, __nv_bfloat16* __restrict__ Cl,
      int M, int N, int K) {
    extern __shared__ char sm[];
    const uint32_t smb = smem_u32(sm);
    const int tid = threadIdx.x;
    const int wid = tid >> 5;
    const int lane = tid & 31;
    const int wm = wid & 1;    // 2 m-blocks of 64
    const int wn = wid >> 1;   // 8 n-blocks of 32
    const int bm = blockIdx.y * 128;
    const int bn = blockIdx.x * 256;
    const int nch = K / HBK;

    auto load_stage = [&](int chunk, int s) {
        const int k0 = chunk * HBK;
        const uint32_t base = smb + s * STAGE_B;
#pragma unroll
        for (int it = 0; it < 3; ++it) {
            const int idx = tid + (it << 9);       // 0..1535
            const int r = idx >> 2, c4 = idx & 3;
            if (r < 128) {
                const uint32_t dst = base + r * SROW + c4 * 16;
                const size_t go = ((size_t)(bm + r) * K + k0 + c4 * 8) * 2;
                cpa16(dst, (const char*)Ah + go);
                cpa16(dst + A_BYTES, (const char*)Al + go);
            } else {
                const int rb = r - 128;
                const uint32_t dst = base + 2 * A_BYTES + rb * SROW + c4 * 16;
                const size_t go = ((size_t)(bn + rb) * K + k0 + c4 * 8) * 2;
                cpa16(dst, (const char*)Bh + go);
                cpa16(dst + B_BYTES, (const char*)Bl + go);
            }
        }
        asm volatile("cp.async.commit_group;");
    };

    float acc[4][4][4];
#pragma unroll
    for (int a = 0; a < 4; ++a)
#pragma unroll
        for (int b = 0; b < 4; ++b)
#pragma unroll
            for (int c = 0; c < 4; ++c) acc[a][b][c] = 0.f;

#pragma unroll
    for (int s = 0; s < NST - 1; ++s)
        if (s < nch) load_stage(s, s);

    const uint32_t a_row = (lane & 15);
    const uint32_t a_koff = ((lane >> 4) << 3);
    const uint32_t b_row = (lane & 7) + (((lane >> 4) & 1) << 3);
    const uint32_t b_koff = (((lane >> 3) & 1) << 3);

    for (int i = 0; i < nch; ++i) {
        if (i + NST - 1 <= nch) {
            asm volatile("cp.async.wait_group %0;" :: "n"(NST - 2));
        } else {
            asm volatile("cp.async.wait_group 0;");
        }
        __syncthreads();
        if (i + NST - 1 < nch) load_stage(i + NST - 1, (i + NST - 1) % NST);

        const uint32_t sb = smb + (i % NST) * STAGE_B;
#pragma unroll
        for (int ks = 0; ks < 2; ++ks) {
            const int k0 = ks * 16;
            uint32_t afh[4][4], afl[4][4];
#pragma unroll
            for (int mi = 0; mi < 4; ++mi) {
                const uint32_t addr =
                    sb + (wm * 64 + mi * 16 + a_row) * SROW + (k0 + a_koff) * 2;
                ldm4(afh[mi], addr);
                ldm4(afl[mi], addr + A_BYTES);
            }
            uint32_t bfh[2][4], bfl[2][4];
#pragma unroll
            for (int g = 0; g < 2; ++g) {
                const uint32_t addr =
                    sb + 2 * A_BYTES + (wn * 32 + g * 16 + b_row) * SROW + (k0 + b_koff) * 2;
                ldm4(bfh[g], addr);
                ldm4(bfl[g], addr + B_BYTES);
            }
#pragma unroll
            for (int mi = 0; mi < 4; ++mi)
#pragma unroll
                for (int ni = 0; ni < 4; ++ni) {
                    const int g = ni >> 1;
                    const int hf = (ni & 1) * 2;
                    mma_bf16(acc[mi][ni], afh[mi], &bfh[g][hf]);
                    mma_bf16(acc[mi][ni], afh[mi], &bfl[g][hf]);
                    mma_bf16(acc[mi][ni], afl[mi], &bfh[g][hf]);
                }
        }
    }

    // epilogue
    const int er = lane >> 2;
    const int ec = (lane & 3) * 2;
#pragma unroll
    for (int mi = 0; mi < 4; ++mi)
#pragma unroll
        for (int ni = 0; ni < 4; ++ni) {
#pragma unroll
            for (int half = 0; half < 2; ++half) {
                const int row = bm + wm * 64 + mi * 16 + er + half * 8;
                const int col = bn + wn * 32 + ni * 8 + ec;
                float v0 = acc[mi][ni][half * 2 + 0] + bias[col];
                float v1 = acc[mi][ni][half * 2 + 1] + bias[col + 1];
                if (EPI == 1) {
                    v0 = fmaxf(v0, 0.f);
                    v1 = fmaxf(v1, 0.f);
                    __nv_bfloat16 h0, l0, h1, l1;
                    split_bf16(v0, h0, l0);
                    split_bf16(v1, h1, l1);
                    const size_t o = (size_t)row * N + col;
                    __nv_bfloat162 hp, lp;
                    hp.x = h0; hp.y = h1;
                    lp.x = l0; lp.y = l1;
                    *(__nv_bfloat162*)(Ch + o) = hp;
                    *(__nv_bfloat162*)(Cl + o) = lp;
                } else if (EPI == 2) {
                    const size_t o = (size_t)row * N + col;
                    const float2 rv = *(const float2*)(res + o);
                    float2 ov;
                    ov.x = v0 + rv.x;
                    ov.y = v1 + rv.y;
                    *(float2*)(Cf + o) = ov;
                } else {
                    const int t = col >> 10;
                    const int cc = col & 1023;
                    const int b = row >> 10, s = row & 1023;
                    const int h = cc >> 6, d = cc & 63;
                    float* dst = (t == 0) ? Cf : (t == 1) ? Cf2 : Cf3;
                    float2 ov;
                    ov.x = v0;
                    ov.y = v1;
                    *(float2*)(dst + (((size_t)(b * NHEAD + h) << 10) + s) * DHEAD + d) = ov;
                }
            }
        }
}

// ---------------- Flash attention, fp32, 64x64 tiles ----------------
__global__ void __launch_bounds__(256) attn_k(const float* __restrict__ Q,
                                              const float* __restrict__ Kg,
                                              const float* __restrict__ Vg,
                                              __nv_bfloat16* __restrict__ CTXh,
                                              __nv_bfloat16* __restrict__ CTXl) {
    extern __shared__ float smf[];
    float* Qs = smf;
    float* Ks = smf + 4352;
    float* Ps = smf + 8704;
    float* Vs = smf + 13056;

    const int tid = threadIdx.x;
    const int ty = tid >> 4;
    const int tx = tid & 15;
    const int bh = blockIdx.y;
    const int q0 = blockIdx.x << 6;
    const size_t base = (size_t)bh << 16;

    const int lrow = tid >> 4;
    const int ld4 = (tid & 15) << 2;

#pragma unroll
    for (int it = 0; it < 4; ++it) {
        const int s = lrow + (it << 4);
        const float4 v = *(const float4*)(Q + base + (size_t)(q0 + s) * DHEAD + ld4);
        Qs[(ld4 + 0) * 68 + s] = v.x;
        Qs[(ld4 + 1) * 68 + s] = v.y;
        Qs[(ld4 + 2) * 68 + s] = v.z;
        Qs[(ld4 + 3) * 68 + s] = v.w;
    }

    float m[4], l[4];
    float4 o[4];
#pragma unroll
    for (int i = 0; i < 4; ++i) {
        m[i] = -1e30f;
        l[i] = 0.0f;
        o[i] = make_float4(0.f, 0.f, 0.f, 0.f);
    }

    for (int kt = 0; kt < 16; ++kt) {
        __syncthreads();
        const float* Kt = Kg + base + ((size_t)(kt << 6)) * DHEAD;
        const float* Vt = Vg + base + ((size_t)(kt << 6)) * DHEAD;
#pragma unroll
        for (int it = 0; it < 4; ++it) {
            const int s = lrow + (it << 4);
            const float4 kv = *(const float4*)(Kt + s * DHEAD + ld4);
            Ks[(ld4 + 0) * 68 + s] = kv.x;
            Ks[(ld4 + 1) * 68 + s] = kv.y;
            Ks[(ld4 + 2) * 68 + s] = kv.z;
            Ks[(ld4 + 3) * 68 + s] = kv.w;
            *(float4*)&Vs[s * 64 + ld4] = *(const float4*)(Vt + s * DHEAD + ld4);
        }
        __syncthreads();

        float s4[4][4];
#pragma unroll
        for (int i = 0; i < 4; ++i)
#pragma unroll
            for (int c = 0; c < 4; ++c) s4[i][c] = 0.f;
#pragma unroll 8
        for (int kk = 0; kk < 64; ++kk) {
            const float4 qf = *(const float4*)&Qs[kk * 68 + (ty << 2)];
            const float4 kf = *(const float4*)&Ks[kk * 68 + (tx << 2)];
            const float qa[4] = {qf.x, qf.y, qf.z, qf.w};
            const float kb[4] = {kf.x, kf.y, kf.z, kf.w};
#pragma unroll
            for (int i = 0; i < 4; ++i)
#pragma unroll
                for (int c = 0; c < 4; ++c) s4[i][c] += qa[i] * kb[c];
        }

#pragma unroll
        for (int i = 0; i < 4; ++i) {
#pragma unroll
            for (int c = 0; c < 4; ++c) s4[i][c] *= 0.125f;
            float tm = fmaxf(fmaxf(s4[i][0], s4[i][1]), fmaxf(s4[i][2], s4[i][3]));
#pragma unroll
            for (int off = 8; off; off >>= 1)
                tm = fmaxf(tm, __shfl_xor_sync(0xffffffffu, tm, off));
            const float mn = fmaxf(m[i], tm);
            const float corr = __expf(m[i] - mn);
            float rsum = 0.f;
#pragma unroll
            for (int c = 0; c < 4; ++c) {
                const float p = __expf(s4[i][c] - mn);
                s4[i][c] = p;
                rsum += p;
            }
#pragma unroll
            for (int off = 8; off; off >>= 1)
                rsum += __shfl_xor_sync(0xffffffffu, rsum, off);
            l[i] = l[i] * corr + rsum;
            o[i].x *= corr; o[i].y *= corr; o[i].z *= corr; o[i].w *= corr;
            m[i] = mn;
#pragma unroll
            for (int c = 0; c < 4; ++c)
                Ps[((tx << 2) + c) * 68 + (ty << 2) + i] = s4[i][c];
        }
        __syncthreads();

#pragma unroll 8
        for (int kk = 0; kk < 64; ++kk) {
            const float4 pf = *(const float4*)&Ps[kk * 68 + (ty << 2)];
            const float4 vf = *(const float4*)&Vs[kk * 64 + (tx << 2)];
            o[0].x += pf.x * vf.x; o[0].y += pf.x * vf.y; o[0].z += pf.x * vf.z; o[0].w += pf.x * vf.w;
            o[1].x += pf.y * vf.x; o[1].y += pf.y * vf.y; o[1].z += pf.y * vf.z; o[1].w += pf.y * vf.w;
            o[2].x += pf.z * vf.x; o[2].y += pf.z * vf.y; o[2].z += pf.z * vf.z; o[2].w += pf.z * vf.w;
            o[3].x += pf.w * vf.x; o[3].y += pf.w * vf.y; o[3].z += pf.w * vf.z; o[3].w += pf.w * vf.w;
        }
    }

    const int b = bh >> 4, h = bh & 15;
#pragma unroll
    for (int i = 0; i < 4; ++i) {
        const float inv = 1.0f / l[i];
        float rv[4] = {o[i].x * inv, o[i].y * inv, o[i].z * inv, o[i].w * inv};
        const size_t off = ((size_t)(b * 1024 + q0 + (ty << 2) + i)) * DM + h * DHEAD + (tx << 2);
        __nv_bfloat16 hh[4], ll[4];
#pragma unroll
        for (int c = 0; c < 4; ++c) split_bf16(rv[c], hh[c], ll[c]);
        __nv_bfloat162 a, bq, c2, d2;
        a.x = hh[0]; a.y = hh[1]; bq.x = hh[2]; bq.y = hh[3];
        c2.x = ll[0]; c2.y = ll[1]; d2.x = ll[2]; d2.y = ll[3];
        *(__nv_bfloat162*)(CTXh + off) = a;
        *(__nv_bfloat162*)(CTXh + off + 2) = bq;
        *(__nv_bfloat162*)(CTXl + off) = c2;
        *(__nv_bfloat162*)(CTXl + off + 2) = d2;
    }
}

// ---------------- launch ----------------
extern "C" void kernel_launch(void* const* d_in, const int* in_sizes, int n_in,
                              void* d_out, int out_size) {
    const float* src = (const float*)d_in[0];
    const float* Wq = (const float*)d_in[1];
    const float* bq = (const float*)d_in[2];
    const float* Wk = (const float*)d_in[3];
    const float* bk = (const float*)d_in[4];
    const float* Wv = (const float*)d_in[5];
    const float* bv = (const float*)d_in[6];
    const float* Wo = (const float*)d_in[7];
    const float* bo = (const float*)d_in[8];
    const float* W1 = (const float*)d_in[9];
    const float* b1 = (const float*)d_in[10];
    const float* W2 = (const float*)d_in[11];
    const float* b2 = (const float*)d_in[12];
    const float* g1 = (const float*)d_in[13];
    const float* be1 = (const float*)d_in[14];
    const float* g2 = (const float*)d_in[15];
    const float* be2 = (const float*)d_in[16];
    float* out = (float*)d_out;

#define SYM(p, s) cudaGetSymbolAddress((void**)&p, s)
    __nv_bfloat16 *Xh, *Xl, *Yh, *Yl, *Chb, *Clb, *Hh, *Hl;
    __nv_bfloat16 *Wqkvh, *Wqkvl, *Woh, *Wol, *W1h, *W1l, *W2h, *W2l;
    float *Qb, *Kb, *Vb, *S2, *bqkv;
    SYM(Xh, g_Xh); SYM(Xl, g_Xl); SYM(Yh, g_Yh); SYM(Yl, g_Yl);
    SYM(Chb, g_Ch); SYM(Clb, g_Cl); SYM(Hh, g_Hh); SYM(Hl, g_Hl);
    SYM(Qb, g_Q); SYM(Kb, g_K); SYM(Vb, g_V); SYM(S2, g_S2); SYM(bqkv, g_bqkv);
    SYM(Wqkvh, g_Wqkvh); SYM(Wqkvl, g_Wqkvl);
    SYM(Woh, g_Woh); SYM(Wol, g_Wol);
    SYM(W1h, g_W1h); SYM(W1l, g_W1l); SYM(W2h, g_W2h); SYM(W2l, g_W2l);
#undef SYM

    const int ATTN_SMEM = 68608;
    cudaFuncSetAttribute(attn_k, cudaFuncAttributeMaxDynamicSharedMemorySize, ATTN_SMEM);
    cudaFuncSetAttribute(hgemm<1>, cudaFuncAttributeMaxDynamicSharedMemorySize, SMEM_G);
    cudaFuncSetAttribute(hgemm<2>, cudaFuncAttributeMaxDynamicSharedMemorySize, SMEM_G);
    cudaFuncSetAttribute(hgemm<3>, cudaFuncAttributeMaxDynamicSharedMemorySize, SMEM_G);

    dim3 cb(32, 8);
    // kernel 1: fused QKV weight conv + bias concat
    wconv3_k<<<dim3(DM / 32, DM / 32, 3), cb>>>(Wq, Wk, Wv, bq, bk, bv, Wqkvh, Wqkvl, bqkv);
    // kernel 2: LN1
    ln_k<<<TOKENS, 256>>>(src, g1, be1, Xh, Xl);
    // kernel 3: Wo conv (so kernel 4 is the profiled hgemm)
    wconv_k<<<dim3(DM / 32, DM / 32), cb>>>(Wo, Woh, Wol, DM, DM);

    // kernel 4: fused QKV GEMM (N=3072) — profiled
    hgemm<3><<<dim3(12, 64), 512, SMEM_G>>>(
        Xh, Xl, Wqkvh, Wqkvl, bqkv, nullptr, Qb, Kb, Vb, nullptr, nullptr, TOKENS, 3 * DM, DM);

    // attention -> CTX bf16 pair
    attn_k<<<dim3(16, 128), 256, ATTN_SMEM>>>(Qb, Kb, Vb, Chb, Clb);

    // Wo + residual(src) -> S2 fp32
    hgemm<2><<<dim3(4, 64), 512, SMEM_G>>>(
        Chb, Clb, Woh, Wol, bo, src, S2, nullptr, nullptr, nullptr, nullptr, TOKENS, DM, DM);

    // LN2 -> Y bf16 pair
    ln_k<<<TOKENS, 256>>>(S2, g2, be2, Yh, Yl);

    // W1 + relu -> H bf16 pair
    wconv_k<<<dim3(DFF / 32, DM / 32), cb>>>(W1, W1h, W1l, DM, DFF);
    hgemm<1><<<dim3(16, 64), 512, SMEM_G>>>(
        Yh, Yl, W1h, W1l, b1, nullptr, nullptr, nullptr, nullptr, Hh, Hl, TOKENS, DFF, DM);

    // W2 + residual(S2) -> out fp32
    wconv_k<<<dim3(DM / 32, DFF / 32), cb>>>(W2, W2h, W2l, DFF, DM);
    hgemm<2><<<dim3(4, 64), 512, SMEM_G>>>(
        Hh, Hl, W2h, W2l, b2, S2, out, nullptr, nullptr, nullptr, nullptr, TOKENS, DM, DFF);
}

// round 9
// speedup vs baseline: 2.7007x; 1.3166x over previous
#include <cuda_runtime.h>
#include <cuda_bf16.h>
#include <cstdint>

#define TOKENS 8192
#define DM 1024
#define DFF 4096
#define NHEAD 16
#define DHEAD 64
#define HALFBUF ((size_t)TOKENS * DM)  // elements in one bf16 half-buffer

// ---------------- scratch (device globals; no runtime alloc allowed) ----------------
__device__ __nv_bfloat16 g_Xh[TOKENS * DM], g_Xl[TOKENS * DM];
__device__ __nv_bfloat16 g_Yh[TOKENS * DM], g_Yl[TOKENS * DM];
__device__ __nv_bfloat16 g_Ch[TOKENS * DM], g_Cl[TOKENS * DM];
__device__ __nv_bfloat16 g_Hh[(size_t)TOKENS * DFF], g_Hl[(size_t)TOKENS * DFF];
__device__ float g_Q[TOKENS * DM];   // holds Qh|Ql bf16 halves
__device__ float g_K[TOKENS * DM];   // holds Kh|Kl
__device__ float g_V[TOKENS * DM];   // holds Vth|Vtl (V transposed [BH,64,S])
__device__ float g_S2[TOKENS * DM];
__device__ float g_bqkv[3 * DM];
__device__ __nv_bfloat16 g_Wqkvh[3 * DM * DM], g_Wqkvl[3 * DM * DM];
__device__ __nv_bfloat16 g_Woh[DM * DM], g_Wol[DM * DM];
__device__ __nv_bfloat16 g_W1h[(size_t)DM * DFF], g_W1l[(size_t)DM * DFF];
__device__ __nv_bfloat16 g_W2h[(size_t)DM * DFF], g_W2l[(size_t)DM * DFF];

// ---------------- PTX helpers ----------------
__device__ __forceinline__ uint32_t smem_u32(const void* p) {
    uint32_t a;
    asm("{ .reg .u64 t; cvta.to.shared.u64 t, %1; cvt.u32.u64 %0, t; }" : "=r"(a) : "l"(p));
    return a;
}
__device__ __forceinline__ void cpa16(uint32_t s, const void* g) {
    asm volatile("cp.async.cg.shared.global [%0], [%1], 16;" :: "r"(s), "l"(g));
}
__device__ __forceinline__ void ldm4(uint32_t* r, uint32_t addr) {
    asm volatile("ldmatrix.sync.aligned.m8n8.x4.shared.b16 {%0,%1,%2,%3}, [%4];"
                 : "=r"(r[0]), "=r"(r[1]), "=r"(r[2]), "=r"(r[3])
                 : "r"(addr));
}
__device__ __forceinline__ void mma_bf16(float* c, const uint32_t* a, const uint32_t* b) {
    asm volatile(
        "mma.sync.aligned.m16n8k16.row.col.f32.bf16.bf16.f32 "
        "{%0,%1,%2,%3}, {%4,%5,%6,%7}, {%8,%9}, {%0,%1,%2,%3};"
        : "+f"(c[0]), "+f"(c[1]), "+f"(c[2]), "+f"(c[3])
        : "r"(a[0]), "r"(a[1]), "r"(a[2]), "r"(a[3]), "r"(b[0]), "r"(b[1]));
}
__device__ __forceinline__ void split_bf16(float v, __nv_bfloat16& h, __nv_bfloat16& l) {
    h = __float2bfloat16(v);
    l = __float2bfloat16(v - __bfloat162float(h));
}
__device__ __forceinline__ uint32_t pack_bf2(__nv_bfloat16 a, __nv_bfloat16 b) {
    __nv_bfloat162 t;
    t.x = a;
    t.y = b;
    return *(uint32_t*)&t;
}

// ------- fused QKV weight transpose+split + bias concat -------
__global__ void __launch_bounds__(256) wconv3_k(const float* __restrict__ Wq,
                                                const float* __restrict__ Wk,
                                                const float* __restrict__ Wv,
                                                const float* __restrict__ bq,
                                                const float* __restrict__ bk,
                                                const float* __restrict__ bv,
                                                __nv_bfloat16* __restrict__ Th,
                                                __nv_bfloat16* __restrict__ Tl,
                                                float* __restrict__ bqkv) {
    const int z = blockIdx.z;
    const float* W = (z == 0) ? Wq : (z == 1) ? Wk : Wv;
    const float* bi = (z == 0) ? bq : (z == 1) ? bk : bv;
    __nv_bfloat16* Tz = Th + (size_t)z * DM * DM;
    __nv_bfloat16* Tzl = Tl + (size_t)z * DM * DM;

    __shared__ float t[32][33];
    const int bx = blockIdx.x * 32;
    const int by = blockIdx.y * 32;
    const int x = threadIdx.x;
    const int y0 = threadIdx.y;
#pragma unroll
    for (int dy = 0; dy < 32; dy += 8)
        t[y0 + dy][x] = W[(size_t)(by + y0 + dy) * DM + bx + x];
    __syncthreads();
#pragma unroll
    for (int dy = 0; dy < 32; dy += 8) {
        const float v = t[x][y0 + dy];
        __nv_bfloat16 h, l;
        split_bf16(v, h, l);
        const size_t o = (size_t)(bx + y0 + dy) * DM + by + x;
        Tz[o] = h;
        Tzl[o] = l;
    }
    if (blockIdx.y == 0 && y0 == 0) bqkv[z * DM + bx + x] = bi[bx + x];
}

// ---------------- generic weight transpose + split ----------------
__global__ void __launch_bounds__(256) wconv_k(const float* __restrict__ W,
                                               __nv_bfloat16* __restrict__ Th,
                                               __nv_bfloat16* __restrict__ Tl,
                                               int K, int N) {
    __shared__ float t[32][33];
    const int bx = blockIdx.x * 32;
    const int by = blockIdx.y * 32;
    const int x = threadIdx.x;
    const int y0 = threadIdx.y;
#pragma unroll
    for (int dy = 0; dy < 32; dy += 8)
        t[y0 + dy][x] = W[(size_t)(by + y0 + dy) * N + bx + x];
    __syncthreads();
#pragma unroll
    for (int dy = 0; dy < 32; dy += 8) {
        const float v = t[x][y0 + dy];
        __nv_bfloat16 h, l;
        split_bf16(v, h, l);
        const size_t o = (size_t)(bx + y0 + dy) * K + by + x;
        Th[o] = h;
        Tl[o] = l;
    }
}

// ---------------- LayerNorm: writes bf16 hi/lo ----------------
__global__ void __launch_bounds__(256) ln_k(const float* __restrict__ x,
                                            const float* __restrict__ g,
                                            const float* __restrict__ be,
                                            __nv_bfloat16* __restrict__ yh,
                                            __nv_bfloat16* __restrict__ yl) {
    const int row = blockIdx.x;
    const int t = threadIdx.x;
    const size_t base = (size_t)row * DM;
    const float4 v = *(const float4*)(x + base + t * 4);
    float s = v.x + v.y + v.z + v.w;
    float q = v.x * v.x + v.y * v.y + v.z * v.z + v.w * v.w;
#pragma unroll
    for (int off = 16; off; off >>= 1) {
        s += __shfl_xor_sync(0xffffffffu, s, off);
        q += __shfl_xor_sync(0xffffffffu, q, off);
    }
    __shared__ float rs[8], rq[8];
    if ((t & 31) == 0) { rs[t >> 5] = s; rq[t >> 5] = q; }
    __syncthreads();
    s = 0.f; q = 0.f;
#pragma unroll
    for (int i = 0; i < 8; ++i) { s += rs[i]; q += rq[i]; }
    const float mu = s * (1.0f / DM);
    const float var = q * (1.0f / DM) - mu * mu;
    const float r = rsqrtf(var + 1e-5f);
    const float4 gv = *(const float4*)(g + t * 4);
    const float4 bv = *(const float4*)(be + t * 4);
    float yv[4];
    yv[0] = (v.x - mu) * r * gv.x + bv.x;
    yv[1] = (v.y - mu) * r * gv.y + bv.y;
    yv[2] = (v.z - mu) * r * gv.z + bv.z;
    yv[3] = (v.w - mu) * r * gv.w + bv.w;
    __nv_bfloat16 h[4], l[4];
#pragma unroll
    for (int i = 0; i < 4; ++i) split_bf16(yv[i], h[i], l[i]);
    __nv_bfloat162 h01, h23, l01, l23;
    h01.x = h[0]; h01.y = h[1]; h23.x = h[2]; h23.y = h[3];
    l01.x = l[0]; l01.y = l[1]; l23.x = l[2]; l23.y = l[3];
    *(__nv_bfloat162*)(yh + base + t * 4) = h01;
    *(__nv_bfloat162*)(yh + base + t * 4 + 2) = h23;
    *(__nv_bfloat162*)(yl + base + t * 4) = l01;
    *(__nv_bfloat162*)(yl + base + t * 4 + 2) = l23;
}

// ---------------- split-bf16 HMMA GEMM, 512 threads, tile 128x256 ----------------
#define HBK 32
#define SROW 80
#define A_BYTES 10240
#define B_BYTES 20480
#define STAGE_B (2 * A_BYTES + 2 * B_BYTES)
#define NST 3
#define SMEM_G (NST * STAGE_B)

template <int EPI>
__global__ void __launch_bounds__(512, 1)
hgemm(const __nv_bfloat16* __restrict__ Ah, const __nv_bfloat16* __restrict__ Al,
      const __nv_bfloat16* __restrict__ Bh, const __nv_bfloat16* __restrict__ Bl,
      const float* __restrict__ bias, const float* __restrict__ res,
      float* __restrict__ Cf, float* __restrict__ Cf2, float* __restrict__ Cf3,
      __nv_bfloat16* __restrict__ Ch, __nv_bfloat16* __restrict__ Cl,
      int M, int N, int K) {
    extern __shared__ char sm[];
    const uint32_t smb = smem_u32(sm);
    const int tid = threadIdx.x;
    const int wid = tid >> 5;
    const int lane = tid & 31;
    const int wm = wid & 1;
    const int wn = wid >> 1;
    const int bm = blockIdx.y * 128;
    const int bn = blockIdx.x * 256;
    const int nch = K / HBK;

    auto load_stage = [&](int chunk, int s) {
        const int k0 = chunk * HBK;
        const uint32_t base = smb + s * STAGE_B;
#pragma unroll
        for (int it = 0; it < 3; ++it) {
            const int idx = tid + (it << 9);
            const int r = idx >> 2, c4 = idx & 3;
            if (r < 128) {
                const uint32_t dst = base + r * SROW + c4 * 16;
                const size_t go = ((size_t)(bm + r) * K + k0 + c4 * 8) * 2;
                cpa16(dst, (const char*)Ah + go);
                cpa16(dst + A_BYTES, (const char*)Al + go);
            } else {
                const int rb = r - 128;
                const uint32_t dst = base + 2 * A_BYTES + rb * SROW + c4 * 16;
                const size_t go = ((size_t)(bn + rb) * K + k0 + c4 * 8) * 2;
                cpa16(dst, (const char*)Bh + go);
                cpa16(dst + B_BYTES, (const char*)Bl + go);
            }
        }
        asm volatile("cp.async.commit_group;");
    };

    float acc[4][4][4];
#pragma unroll
    for (int a = 0; a < 4; ++a)
#pragma unroll
        for (int b = 0; b < 4; ++b)
#pragma unroll
            for (int c = 0; c < 4; ++c) acc[a][b][c] = 0.f;

#pragma unroll
    for (int s = 0; s < NST - 1; ++s)
        if (s < nch) load_stage(s, s);

    const uint32_t a_row = (lane & 15);
    const uint32_t a_koff = ((lane >> 4) << 3);
    const uint32_t b_row = (lane & 7) + (((lane >> 4) & 1) << 3);
    const uint32_t b_koff = (((lane >> 3) & 1) << 3);

    for (int i = 0; i < nch; ++i) {
        if (i + NST - 1 <= nch) {
            asm volatile("cp.async.wait_group %0;" :: "n"(NST - 2));
        } else {
            asm volatile("cp.async.wait_group 0;");
        }
        __syncthreads();
        if (i + NST - 1 < nch) load_stage(i + NST - 1, (i + NST - 1) % NST);

        const uint32_t sb = smb + (i % NST) * STAGE_B;
#pragma unroll
        for (int ks = 0; ks < 2; ++ks) {
            const int k0 = ks * 16;
            uint32_t afh[4][4], afl[4][4];
#pragma unroll
            for (int mi = 0; mi < 4; ++mi) {
                const uint32_t addr =
                    sb + (wm * 64 + mi * 16 + a_row) * SROW + (k0 + a_koff) * 2;
                ldm4(afh[mi], addr);
                ldm4(afl[mi], addr + A_BYTES);
            }
            uint32_t bfh[2][4], bfl[2][4];
#pragma unroll
            for (int g = 0; g < 2; ++g) {
                const uint32_t addr =
                    sb + 2 * A_BYTES + (wn * 32 + g * 16 + b_row) * SROW + (k0 + b_koff) * 2;
                ldm4(bfh[g], addr);
                ldm4(bfl[g], addr + B_BYTES);
            }
#pragma unroll
            for (int mi = 0; mi < 4; ++mi)
#pragma unroll
                for (int ni = 0; ni < 4; ++ni) {
                    const int g = ni >> 1;
                    const int hf = (ni & 1) * 2;
                    mma_bf16(acc[mi][ni], afh[mi], &bfh[g][hf]);
                    mma_bf16(acc[mi][ni], afh[mi], &bfl[g][hf]);
                    mma_bf16(acc[mi][ni], afl[mi], &bfh[g][hf]);
                }
        }
    }

    // epilogue
    const int er = lane >> 2;
    const int ec = (lane & 3) * 2;
#pragma unroll
    for (int mi = 0; mi < 4; ++mi)
#pragma unroll
        for (int ni = 0; ni < 4; ++ni) {
#pragma unroll
            for (int half = 0; half < 2; ++half) {
                const int row = bm + wm * 64 + mi * 16 + er + half * 8;
                const int col = bn + wn * 32 + ni * 8 + ec;
                float v0 = acc[mi][ni][half * 2 + 0] + bias[col];
                float v1 = acc[mi][ni][half * 2 + 1] + bias[col + 1];
                if (EPI == 1) {
                    v0 = fmaxf(v0, 0.f);
                    v1 = fmaxf(v1, 0.f);
                    __nv_bfloat16 h0, l0, h1, l1;
                    split_bf16(v0, h0, l0);
                    split_bf16(v1, h1, l1);
                    const size_t o = (size_t)row * N + col;
                    *(__nv_bfloat162*)(Ch + o) = __nv_bfloat162{h0, h1};
                    *(__nv_bfloat162*)(Cl + o) = __nv_bfloat162{l0, l1};
                } else if (EPI == 2) {
                    const size_t o = (size_t)row * N + col;
                    const float2 rv = *(const float2*)(res + o);
                    float2 ov;
                    ov.x = v0 + rv.x;
                    ov.y = v1 + rv.y;
                    *(float2*)(Cf + o) = ov;
                } else {  // EPI == 3: QKV scatter to bf16 pairs; Q scaled; V transposed
                    const int t = col >> 10;
                    const int cc = col & 1023;
                    const int b = row >> 10, s = row & 1023;
                    const int h = cc >> 6, d = cc & 63;
                    if (t == 0) { v0 *= 0.125f; v1 *= 0.125f; }
                    __nv_bfloat16 h0, l0, h1, l1;
                    split_bf16(v0, h0, l0);
                    split_bf16(v1, h1, l1);
                    if (t < 2) {
                        __nv_bfloat16* Dh = (__nv_bfloat16*)(t == 0 ? Cf : Cf2);
                        __nv_bfloat16* Dl = Dh + HALFBUF;
                        const size_t o = ((size_t)(b * NHEAD + h) * 1024 + s) * DHEAD + d;
                        *(__nv_bfloat162*)(Dh + o) = __nv_bfloat162{h0, h1};
                        *(__nv_bfloat162*)(Dl + o) = __nv_bfloat162{l0, l1};
                    } else {
                        __nv_bfloat16* Dh = (__nv_bfloat16*)Cf3;
                        __nv_bfloat16* Dl = Dh + HALFBUF;
                        const size_t o0 = ((size_t)(b * NHEAD + h) * DHEAD + d) * 1024 + s;
                        Dh[o0] = h0;
                        Dl[o0] = l0;
                        Dh[o0 + 1024] = h1;
                        Dl[o0 + 1024] = l1;
                    }
                }
            }
        }
}

// ---------------- split-bf16 HMMA flash attention ----------------
// Q,K: bf16 hi/lo [BH, S, 64] (Q pre-scaled 0.125); Vt: bf16 hi/lo [BH, 64, S].
// CTA: 128 q rows, 8 warps (16 rows each), kv tiles of 64, 3-stage cp.async.
#define AST 144          // smem row stride bytes (64 bf16 + 8 pad)
#define AQ_B 18432       // 128 * 144 (one of hi/lo)
#define AKV_T 9216       // 64 * 144
#define AKV_STAGE 36864  // Kh,Kl,Vh,Vl tiles
#define ATT_SMEM (2 * AQ_B + 3 * AKV_STAGE)  // 147456

__global__ void __launch_bounds__(256, 1)
attn_k(const __nv_bfloat16* __restrict__ Qhp, const __nv_bfloat16* __restrict__ Khp,
       const __nv_bfloat16* __restrict__ Vhp,
       __nv_bfloat16* __restrict__ CTXh, __nv_bfloat16* __restrict__ CTXl) {
    const __nv_bfloat16* Qlp = Qhp + HALFBUF;
    const __nv_bfloat16* Klp = Khp + HALFBUF;
    const __nv_bfloat16* Vlp = Vhp + HALFBUF;

    extern __shared__ char sm[];
    const uint32_t smb = smem_u32(sm);
    const uint32_t QS = smb;
    const uint32_t KST0 = smb + 2 * AQ_B;

    const int tid = threadIdx.x;
    const int wid = tid >> 5;
    const int lane = tid & 31;
    const int bh = blockIdx.y;
    const int q0 = blockIdx.x << 7;

    // Q tile load (no commit; joins group of kv tile 0)
    {
#pragma unroll
        for (int it = 0; it < 8; ++it) {
            const int idx = tid + (it << 8);
            const int hl = idx >> 10;
            const int rem = idx & 1023;
            const int r = rem >> 3;
            const int c = rem & 7;
            const uint32_t dst = QS + hl * AQ_B + r * AST + c * 16;
            const char* src = (const char*)(hl ? Qlp : Qhp) +
                              (size_t)((bh << 10) + q0 + r) * 128 + c * 16;
            cpa16(dst, src);
        }
    }

    auto load_kv = [&](int kt, int s) {
        const uint32_t base = KST0 + s * AKV_STAGE;
#pragma unroll
        for (int it = 0; it < 8; ++it) {
            const int idx = tid + (it << 8);
            const int tensor = idx >> 10;
            const int rem = idx & 1023;
            const int r = rem >> 4;
            const int c = (rem >> 1) & 7;
            const int hl = rem & 1;
            if (tensor == 0) {
                const uint32_t dst = base + hl * AKV_T + r * AST + c * 16;
                const char* src = (const char*)(hl ? Klp : Khp) +
                                  (size_t)((bh << 10) + (kt << 6) + r) * 128 + c * 16;
                cpa16(dst, src);
            } else {
                const uint32_t dst = base + 2 * AKV_T + hl * AKV_T + r * AST + c * 16;
                const char* src = (const char*)(hl ? Vlp : Vhp) +
                                  (((size_t)(bh * 64 + r) << 10) + (kt << 6)) * 2 + c * 16;
                cpa16(dst, src);
            }
        }
        asm volatile("cp.async.commit_group;");
    };

    load_kv(0, 0);  // group 0 = Q + KV0
    load_kv(1, 1);  // group 1

    float m0 = -1e30f, m1 = -1e30f, l0 = 0.f, l1 = 0.f;
    float oacc[8][4];
#pragma unroll
    for (int i = 0; i < 8; ++i)
#pragma unroll
        for (int j = 0; j < 4; ++j) oacc[i][j] = 0.f;

    const uint32_t a_row = (lane & 15);
    const uint32_t a_koff = ((lane >> 4) << 3);
    const uint32_t b_row = (lane & 7) + (((lane >> 4) & 1) << 3);
    const uint32_t b_koff = (((lane >> 3) & 1) << 3);

    for (int kt = 0; kt < 16; ++kt) {
        if (kt + 2 <= 16) {
            asm volatile("cp.async.wait_group 1;");
        } else {
            asm volatile("cp.async.wait_group 0;");
        }
        __syncthreads();
        if (kt + 2 < 16) load_kv(kt + 2, (kt + 2) % 3);

        const uint32_t st = KST0 + (kt % 3) * AKV_STAGE;

        // ---- S = Q K^T (split, fp32 acc) ----
        float sacc[8][4];
#pragma unroll
        for (int i = 0; i < 8; ++i)
#pragma unroll
            for (int j = 0; j < 4; ++j) sacc[i][j] = 0.f;
#pragma unroll
        for (int kc = 0; kc < 4; ++kc) {
            uint32_t afh[4], afl[4];
            const uint32_t aaddr = QS + (wid * 16 + a_row) * AST + (kc * 16 + a_koff) * 2;
            ldm4(afh, aaddr);
            ldm4(afl, aaddr + AQ_B);
            uint32_t bkh[4][4], bkl[4][4];
#pragma unroll
            for (int g = 0; g < 4; ++g) {
                const uint32_t baddr = st + (g * 16 + b_row) * AST + (kc * 16 + b_koff) * 2;
                ldm4(bkh[g], baddr);
                ldm4(bkl[g], baddr + AKV_T);
            }
#pragma unroll
            for (int ni = 0; ni < 8; ++ni) {
                const int g = ni >> 1;
                const int hf = (ni & 1) * 2;
                mma_bf16(sacc[ni], afh, &bkh[g][hf]);
                mma_bf16(sacc[ni], afh, &bkl[g][hf]);
                mma_bf16(sacc[ni], afl, &bkh[g][hf]);
            }
        }

        // ---- online softmax (rows g=lane>>2 and g+8) ----
        float rmax0 = -1e30f, rmax1 = -1e30f;
#pragma unroll
        for (int ni = 0; ni < 8; ++ni) {
            rmax0 = fmaxf(rmax0, fmaxf(sacc[ni][0], sacc[ni][1]));
            rmax1 = fmaxf(rmax1, fmaxf(sacc[ni][2], sacc[ni][3]));
        }
        rmax0 = fmaxf(rmax0, __shfl_xor_sync(0xffffffffu, rmax0, 1));
        rmax0 = fmaxf(rmax0, __shfl_xor_sync(0xffffffffu, rmax0, 2));
        rmax1 = fmaxf(rmax1, __shfl_xor_sync(0xffffffffu, rmax1, 1));
        rmax1 = fmaxf(rmax1, __shfl_xor_sync(0xffffffffu, rmax1, 2));
        const float mn0 = fmaxf(m0, rmax0);
        const float mn1 = fmaxf(m1, rmax1);
        const float cor0 = __expf(m0 - mn0);
        const float cor1 = __expf(m1 - mn1);
        float rs0 = 0.f, rs1 = 0.f;
#pragma unroll
        for (int ni = 0; ni < 8; ++ni) {
            sacc[ni][0] = __expf(sacc[ni][0] - mn0);
            sacc[ni][1] = __expf(sacc[ni][1] - mn0);
            sacc[ni][2] = __expf(sacc[ni][2] - mn1);
            sacc[ni][3] = __expf(sacc[ni][3] - mn1);
            rs0 += sacc[ni][0] + sacc[ni][1];
            rs1 += sacc[ni][2] + sacc[ni][3];
        }
        rs0 += __shfl_xor_sync(0xffffffffu, rs0, 1);
        rs0 += __shfl_xor_sync(0xffffffffu, rs0, 2);
        rs1 += __shfl_xor_sync(0xffffffffu, rs1, 1);
        rs1 += __shfl_xor_sync(0xffffffffu, rs1, 2);
        l0 = l0 * cor0 + rs0;
        l1 = l1 * cor1 + rs1;
        m0 = mn0;
        m1 = mn1;
#pragma unroll
        for (int ni = 0; ni < 8; ++ni) {
            oacc[ni][0] *= cor0;
            oacc[ni][1] *= cor0;
            oacc[ni][2] *= cor1;
            oacc[ni][3] *= cor1;
        }

        // ---- O += P V (split P, fp32 acc) ----
#pragma unroll
        for (int j = 0; j < 4; ++j) {
            uint32_t pah[4], pal[4];
#pragma unroll
            for (int tt = 0; tt < 2; ++tt) {
                const float* sc = sacc[2 * j + tt];
#pragma unroll
                for (int q = 0; q < 2; ++q) {
                    const float v0 = sc[2 * q], v1 = sc[2 * q + 1];
                    __nv_bfloat16 h0, e0, h1, e1;
                    split_bf16(v0, h0, e0);
                    split_bf16(v1, h1, e1);
                    pah[2 * tt + q] = pack_bf2(h0, h1);
                    pal[2 * tt + q] = pack_bf2(e0, e1);
                }
            }
            uint32_t bvh[4][4], bvl[4][4];
#pragma unroll
            for (int g = 0; g < 4; ++g) {
                const uint32_t baddr =
                    st + 2 * AKV_T + (g * 16 + b_row) * AST + (j * 16 + b_koff) * 2;
                ldm4(bvh[g], baddr);
                ldm4(bvl[g], baddr + AKV_T);
            }
#pragma unroll
            for (int ni = 0; ni < 8; ++ni) {
                const int g = ni >> 1;
                const int hf = (ni & 1) * 2;
                mma_bf16(oacc[ni], pah, &bvh[g][hf]);
                mma_bf16(oacc[ni], pah, &bvl[g][hf]);
                mma_bf16(oacc[ni], pal, &bvh[g][hf]);
            }
        }
    }

    // ---- epilogue: O /= l, write CTX bf16 pairs [B, S, D] ----
    const float inv0 = 1.0f / l0;
    const float inv1 = 1.0f / l1;
    const int b = bh >> 4, h = bh & 15;
    const int row0 = q0 + wid * 16 + (lane >> 2);
    const int ec = (lane & 3) * 2;
#pragma unroll
    for (int ni = 0; ni < 8; ++ni) {
        const int col = h * 64 + ni * 8 + ec;
        {
            const float v0 = oacc[ni][0] * inv0, v1 = oacc[ni][1] * inv0;
            __nv_bfloat16 h0, e0, h1, e1;
            split_bf16(v0, h0, e0);
            split_bf16(v1, h1, e1);
            const size_t o = ((size_t)(b * 1024 + row0) * DM) + col;
            *(__nv_bfloat162*)(CTXh + o) = __nv_bfloat162{h0, h1};
            *(__nv_bfloat162*)(CTXl + o) = __nv_bfloat162{e0, e1};
        }
        {
            const float v0 = oacc[ni][2] * inv1, v1 = oacc[ni][3] * inv1;
            __nv_bfloat16 h0, e0, h1, e1;
            split_bf16(v0, h0, e0);
            split_bf16(v1, h1, e1);
            const size_t o = ((size_t)(b * 1024 + row0 + 8) * DM) + col;
            *(__nv_bfloat162*)(CTXh + o) = __nv_bfloat162{h0, h1};
            *(__nv_bfloat162*)(CTXl + o) = __nv_bfloat162{e0, e1};
        }
    }
}

// ---------------- launch ----------------
extern "C" void kernel_launch(void* const* d_in, const int* in_sizes, int n_in,
                              void* d_out, int out_size) {
    const float* src = (const float*)d_in[0];
    const float* Wq = (const float*)d_in[1];
    const float* bq = (const float*)d_in[2];
    const float* Wk = (const float*)d_in[3];
    const float* bk = (const float*)d_in[4];
    const float* Wv = (const float*)d_in[5];
    const float* bv = (const float*)d_in[6];
    const float* Wo = (const float*)d_in[7];
    const float* bo = (const float*)d_in[8];
    const float* W1 = (const float*)d_in[9];
    const float* b1 = (const float*)d_in[10];
    const float* W2 = (const float*)d_in[11];
    const float* b2 = (const float*)d_in[12];
    const float* g1 = (const float*)d_in[13];
    const float* be1 = (const float*)d_in[14];
    const float* g2 = (const float*)d_in[15];
    const float* be2 = (const float*)d_in[16];
    float* out = (float*)d_out;

#define SYM(p, s) cudaGetSymbolAddress((void**)&p, s)
    __nv_bfloat16 *Xh, *Xl, *Yh, *Yl, *Chb, *Clb, *Hh, *Hl;
    __nv_bfloat16 *Wqkvh, *Wqkvl, *Woh, *Wol, *W1h, *W1l, *W2h, *W2l;
    float *Qb, *Kb, *Vb, *S2, *bqkv;
    SYM(Xh, g_Xh); SYM(Xl, g_Xl); SYM(Yh, g_Yh); SYM(Yl, g_Yl);
    SYM(Chb, g_Ch); SYM(Clb, g_Cl); SYM(Hh, g_Hh); SYM(Hl, g_Hl);
    SYM(Qb, g_Q); SYM(Kb, g_K); SYM(Vb, g_V); SYM(S2, g_S2); SYM(bqkv, g_bqkv);
    SYM(Wqkvh, g_Wqkvh); SYM(Wqkvl, g_Wqkvl);
    SYM(Woh, g_Woh); SYM(Wol, g_Wol);
    SYM(W1h, g_W1h); SYM(W1l, g_W1l); SYM(W2h, g_W2h); SYM(W2l, g_W2l);
#undef SYM

    cudaFuncSetAttribute(attn_k, cudaFuncAttributeMaxDynamicSharedMemorySize, ATT_SMEM);
    cudaFuncSetAttribute(hgemm<1>, cudaFuncAttributeMaxDynamicSharedMemorySize, SMEM_G);
    cudaFuncSetAttribute(hgemm<2>, cudaFuncAttributeMaxDynamicSharedMemorySize, SMEM_G);
    cudaFuncSetAttribute(hgemm<3>, cudaFuncAttributeMaxDynamicSharedMemorySize, SMEM_G);

    dim3 cb(32, 8);
    // kernel 1: fused QKV weight conv + bias concat
    wconv3_k<<<dim3(DM / 32, DM / 32, 3), cb>>>(Wq, Wk, Wv, bq, bk, bv, Wqkvh, Wqkvl, bqkv);
    // kernel 2: LN1
    ln_k<<<TOKENS, 256>>>(src, g1, be1, Xh, Xl);
    // kernel 3: Wo conv
    wconv_k<<<dim3(DM / 32, DM / 32), cb>>>(Wo, Woh, Wol, DM, DM);

    // kernel 4: fused QKV GEMM (N=3072) — profiled control
    hgemm<3><<<dim3(12, 64), 512, SMEM_G>>>(
        Xh, Xl, Wqkvh, Wqkvl, bqkv, nullptr, Qb, Kb, Vb, nullptr, nullptr, TOKENS, 3 * DM, DM);

    // kernel 5: HMMA flash attention -> CTX bf16 pair
    attn_k<<<dim3(8, 128), 256, ATT_SMEM>>>(
        (const __nv_bfloat16*)Qb, (const __nv_bfloat16*)Kb, (const __nv_bfloat16*)Vb, Chb, Clb);

    // Wo + residual(src) -> S2 fp32
    hgemm<2><<<dim3(4, 64), 512, SMEM_G>>>(
        Chb, Clb, Woh, Wol, bo, src, S2, nullptr, nullptr, nullptr, nullptr, TOKENS, DM, DM);

    // LN2 -> Y bf16 pair
    ln_k<<<TOKENS, 256>>>(S2, g2, be2, Yh, Yl);

    // W1 + relu -> H bf16 pair
    wconv_k<<<dim3(DFF / 32, DM / 32), cb>>>(W1, W1h, W1l, DM, DFF);
    hgemm<1><<<dim3(16, 64), 512, SMEM_G>>>(
        Yh, Yl, W1h, W1l, b1, nullptr, nullptr, nullptr, nullptr, Hh, Hl, TOKENS, DFF, DM);

    // W2 + residual(S2) -> out fp32
    wconv_k<<<dim3(DM / 32, DFF / 32), cb>>>(W2, W2h, W2l, DFF, DM);
    hgemm<2><<<dim3(4, 64), 512, SMEM_G>>>(
        Hh, Hl, W2h, W2l, b2, S2, out, nullptr, nullptr, nullptr, nullptr, TOKENS, DM, DFF);
}